// round 2
// baseline (speedup 1.0000x reference)
#include <cuda_runtime.h>

#define BB 16
#define SS 2048
#define EE 512
#define HH 64
#define MROWS (BB*SS)   // 32768

// Scratch (allocation-free rule: __device__ globals)
__device__ float g_q[MROWS*HH];
__device__ float g_k[MROWS*HH];
__device__ float g_v[MROWS*HH];
__device__ int   g_seqlen[BB];

// ---------------------------------------------------------------------------
// seq_lengths may arrive as int32 or int64 depending on how the reference's
// jnp.int64 cast was serialized (JAX x64 is off by default -> int32).
// Detect: int64 LE => words 1,3,..,15 are the zero high-halves and even words
// are valid lengths in [0, SS]. Random int32 lengths fail that w.p. ~1.
// ---------------------------------------------------------------------------
__global__ void normalize_seqlen_kernel(const int* __restrict__ raw)
{
    if (threadIdx.x != 0 || blockIdx.x != 0) return;
    bool looks64 = true;
    #pragma unroll
    for (int i = 0; i < 8; ++i) {
        int lo = raw[2 * i], hi = raw[2 * i + 1];
        if (hi != 0 || lo < 0 || lo > SS) looks64 = false;
    }
    #pragma unroll
    for (int b = 0; b < BB; ++b) {
        int v = looks64 ? raw[2 * b] : raw[b];
        if (v < 0) v = 0;
        if (v > SS) v = SS;
        g_seqlen[b] = v;
    }
}

// ---------------------------------------------------------------------------
// Projection: out = input @ W  (M=32768, K=512, N=64), masked for q,k
// grid (512, 3), block 256. BM=64, BN=64, BK=16, 4x4 microtile/thread.
// ---------------------------------------------------------------------------
__global__ __launch_bounds__(256) void proj_kernel(
    const float* __restrict__ input,
    const float* __restrict__ Wq,
    const float* __restrict__ Wk,
    const float* __restrict__ Wv)
{
    const int w = blockIdx.y;                       // 0:q 1:k 2:v
    const float* __restrict__ W = (w == 0) ? Wq : (w == 1) ? Wk : Wv;
    float* __restrict__ out = (w == 0) ? g_q : (w == 1) ? g_k : g_v;

    __shared__ float As[16][65];   // A^T tile: [k][m], padded
    __shared__ float Bs[16][64];   // B tile: [k][n]

    const int tid = threadIdx.x;
    const int tx = tid & 15;          // n-group
    const int ty = tid >> 4;          // m-group
    const int tx4 = tx * 4, ty4 = ty * 4;
    const int row0 = blockIdx.x * 64;

    const int ar  = tid >> 2;         // 0..63  (A tile row)
    const int ac4 = tid & 3;          // 0..3   (A tile col/4)
    const int br  = tid >> 4;         // 0..15  (B tile row)
    const int bc4 = tid & 15;         // 0..15  (B tile col/4)

    float c[4][4] = {};

    for (int k0 = 0; k0 < EE; k0 += 16) {
        float4 av = *reinterpret_cast<const float4*>(
            &input[(size_t)(row0 + ar) * EE + k0 + ac4 * 4]);
        As[ac4 * 4 + 0][ar] = av.x;
        As[ac4 * 4 + 1][ar] = av.y;
        As[ac4 * 4 + 2][ar] = av.z;
        As[ac4 * 4 + 3][ar] = av.w;

        *reinterpret_cast<float4*>(&Bs[br][bc4 * 4]) =
            *reinterpret_cast<const float4*>(&W[(size_t)(k0 + br) * HH + bc4 * 4]);
        __syncthreads();

        #pragma unroll
        for (int kk = 0; kk < 16; ++kk) {
            float a0 = As[kk][ty4 + 0];
            float a1 = As[kk][ty4 + 1];
            float a2 = As[kk][ty4 + 2];
            float a3 = As[kk][ty4 + 3];
            float4 b = *reinterpret_cast<const float4*>(&Bs[kk][tx4]);
            c[0][0] += a0 * b.x; c[0][1] += a0 * b.y; c[0][2] += a0 * b.z; c[0][3] += a0 * b.w;
            c[1][0] += a1 * b.x; c[1][1] += a1 * b.y; c[1][2] += a1 * b.z; c[1][3] += a1 * b.w;
            c[2][0] += a2 * b.x; c[2][1] += a2 * b.y; c[2][2] += a2 * b.z; c[2][3] += a2 * b.w;
            c[3][0] += a3 * b.x; c[3][1] += a3 * b.y; c[3][2] += a3 * b.z; c[3][3] += a3 * b.w;
        }
        __syncthreads();
    }

    #pragma unroll
    for (int i = 0; i < 4; ++i) {
        int grow = row0 + ty4 + i;
        int bb = grow >> 11;          // /2048
        int s  = grow & 2047;
        bool z = (w < 2) && (s >= g_seqlen[bb]);
        float4 v;
        v.x = z ? 0.f : c[i][0];
        v.y = z ? 0.f : c[i][1];
        v.z = z ? 0.f : c[i][2];
        v.w = z ? 0.f : c[i][3];
        *reinterpret_cast<float4*>(&out[(size_t)grow * HH + tx4]) = v;
    }
}

// ---------------------------------------------------------------------------
// Flash attention over full 2048 columns (reference has NO score masking;
// k rows are pre-zeroed so padded columns score exactly 0, matching softmax).
// grid (32, 16), block 256. 64 q-rows per block, key tiles of 64.
// ---------------------------------------------------------------------------
__global__ __launch_bounds__(256) void attn_kernel(float* __restrict__ out)
{
    extern __shared__ float sm[];
    float* Qs = sm;                  // [64][64] natural [r][h], pre-scaled
    float* Ks = Qs + 64 * 64;        // [64][65] transposed [h][t]; reused as Ps [t][r]
    float* Vs = Ks + 64 * 65;        // [64][64] natural [t][h]

    const int b  = blockIdx.y;
    const int q0 = blockIdx.x * 64;
    const float* __restrict__ qg = g_q + (size_t)b * SS * HH;
    const float* __restrict__ kg = g_k + (size_t)b * SS * HH;
    const float* __restrict__ vg = g_v + (size_t)b * SS * HH;

    const int tid = threadIdx.x;
    const int tx = tid & 15, ty = tid >> 4;
    const int tx4 = tx * 4, ty4 = ty * 4;

    // Loaders: lane%16 = col float4, (tid/16)*4+u = row  -> coalesced
    const int lc4 = tid & 15;
    const int lrb = (tid >> 4) * 4;

    // Load Q tile (scaled by 1/sqrt(64) = 0.125)
    #pragma unroll
    for (int u = 0; u < 4; ++u) {
        float4 qv = *reinterpret_cast<const float4*>(
            &qg[(size_t)(q0 + lrb + u) * HH + lc4 * 4]);
        qv.x *= 0.125f; qv.y *= 0.125f; qv.z *= 0.125f; qv.w *= 0.125f;
        *reinterpret_cast<float4*>(&Qs[(lrb + u) * 64 + lc4 * 4]) = qv;
    }

    float m[4], l[4], o[4][4];
    #pragma unroll
    for (int i = 0; i < 4; ++i) {
        m[i] = -INFINITY; l[i] = 0.f;
        o[i][0] = o[i][1] = o[i][2] = o[i][3] = 0.f;
    }

    for (int t0 = 0; t0 < SS; t0 += 64) {
        __syncthreads();   // prev O-GEMM done before K/V overwrite
        // Load K (transpose into [h][t], pad 65) and V (natural)
        #pragma unroll
        for (int u = 0; u < 4; ++u) {
            int t = lrb + u;
            float4 kv = *reinterpret_cast<const float4*>(
                &kg[(size_t)(t0 + t) * HH + lc4 * 4]);
            Ks[(lc4 * 4 + 0) * 65 + t] = kv.x;
            Ks[(lc4 * 4 + 1) * 65 + t] = kv.y;
            Ks[(lc4 * 4 + 2) * 65 + t] = kv.z;
            Ks[(lc4 * 4 + 3) * 65 + t] = kv.w;
            *reinterpret_cast<float4*>(&Vs[t * 64 + lc4 * 4]) =
                *reinterpret_cast<const float4*>(&vg[(size_t)(t0 + t) * HH + lc4 * 4]);
        }
        __syncthreads();

        // S = Q K^T  (rows ty4+i, key-cols tx4+j)
        float sacc[4][4] = {};
        #pragma unroll
        for (int h = 0; h < 64; ++h) {
            float a0 = Qs[(ty4 + 0) * 64 + h];
            float a1 = Qs[(ty4 + 1) * 64 + h];
            float a2 = Qs[(ty4 + 2) * 64 + h];
            float a3 = Qs[(ty4 + 3) * 64 + h];
            float b0 = Ks[h * 65 + tx4 + 0];
            float b1 = Ks[h * 65 + tx4 + 1];
            float b2 = Ks[h * 65 + tx4 + 2];
            float b3 = Ks[h * 65 + tx4 + 3];
            sacc[0][0] += a0 * b0; sacc[0][1] += a0 * b1; sacc[0][2] += a0 * b2; sacc[0][3] += a0 * b3;
            sacc[1][0] += a1 * b0; sacc[1][1] += a1 * b1; sacc[1][2] += a1 * b2; sacc[1][3] += a1 * b3;
            sacc[2][0] += a2 * b0; sacc[2][1] += a2 * b1; sacc[2][2] += a2 * b2; sacc[2][3] += a2 * b3;
            sacc[3][0] += a3 * b0; sacc[3][1] += a3 * b1; sacc[3][2] += a3 * b2; sacc[3][3] += a3 * b3;
        }

        // Online softmax per row (reduce across the 16 tx lanes of each half-warp)
        #pragma unroll
        for (int i = 0; i < 4; ++i) {
            float mt = fmaxf(fmaxf(sacc[i][0], sacc[i][1]), fmaxf(sacc[i][2], sacc[i][3]));
            #pragma unroll
            for (int off = 8; off >= 1; off >>= 1)
                mt = fmaxf(mt, __shfl_xor_sync(0xffffffffu, mt, off));
            float mnew = fmaxf(m[i], mt);
            float alpha = __expf(m[i] - mnew);
            m[i] = mnew;
            float ssum = 0.f;
            #pragma unroll
            for (int j = 0; j < 4; ++j) {
                sacc[i][j] = __expf(sacc[i][j] - mnew);
                ssum += sacc[i][j];
            }
            #pragma unroll
            for (int off = 8; off >= 1; off >>= 1)
                ssum += __shfl_xor_sync(0xffffffffu, ssum, off);
            l[i] = l[i] * alpha + ssum;
            o[i][0] *= alpha; o[i][1] *= alpha; o[i][2] *= alpha; o[i][3] *= alpha;
        }

        __syncthreads();   // all S-GEMM reads of Ks done
        // Write P transposed into Ks buffer: Ps[t][r]
        #pragma unroll
        for (int i = 0; i < 4; ++i)
            #pragma unroll
            for (int j = 0; j < 4; ++j)
                Ks[(tx4 + j) * 65 + ty4 + i] = sacc[i][j];
        __syncthreads();

        // O += P @ V   (rows ty4+i, head-cols tx4+j)
        #pragma unroll
        for (int t = 0; t < 64; ++t) {
            float a0 = Ks[t * 65 + ty4 + 0];
            float a1 = Ks[t * 65 + ty4 + 1];
            float a2 = Ks[t * 65 + ty4 + 2];
            float a3 = Ks[t * 65 + ty4 + 3];
            float4 bv = *reinterpret_cast<const float4*>(&Vs[t * 64 + tx4]);
            o[0][0] += a0 * bv.x; o[0][1] += a0 * bv.y; o[0][2] += a0 * bv.z; o[0][3] += a0 * bv.w;
            o[1][0] += a1 * bv.x; o[1][1] += a1 * bv.y; o[1][2] += a1 * bv.z; o[1][3] += a1 * bv.w;
            o[2][0] += a2 * bv.x; o[2][1] += a2 * bv.y; o[2][2] += a2 * bv.z; o[2][3] += a2 * bv.w;
            o[3][0] += a3 * bv.x; o[3][1] += a3 * bv.y; o[3][2] += a3 * bv.z; o[3][3] += a3 * bv.w;
        }
    }

    // Epilogue: normalize and store (l > 0 always: 2048 positive terms)
    #pragma unroll
    for (int i = 0; i < 4; ++i) {
        float inv = 1.0f / l[i];
        float4 ov;
        ov.x = o[i][0] * inv; ov.y = o[i][1] * inv;
        ov.z = o[i][2] * inv; ov.w = o[i][3] * inv;
        *reinterpret_cast<float4*>(
            &out[((size_t)b * SS + q0 + ty4 + i) * HH + tx4]) = ov;
    }
}

// ---------------------------------------------------------------------------
extern "C" void kernel_launch(void* const* d_in, const int* in_sizes, int n_in,
                              void* d_out, int out_size)
{
    const float* input  = (const float*)d_in[0];
    const int*   seqraw = (const int*)d_in[1];
    const float* Wq     = (const float*)d_in[2];
    const float* Wk     = (const float*)d_in[3];
    const float* Wv     = (const float*)d_in[4];
    float*       out    = (float*)d_out;

    const int attn_smem = (64 * 64 + 64 * 65 + 64 * 64) * (int)sizeof(float); // 49408
    cudaFuncSetAttribute(attn_kernel,
                         cudaFuncAttributeMaxDynamicSharedMemorySize, attn_smem);

    normalize_seqlen_kernel<<<1, 32>>>(seqraw);

    dim3 pgrid(MROWS / 64, 3);
    proj_kernel<<<pgrid, 256>>>(input, Wq, Wk, Wv);

    dim3 agrid(SS / 64, BB);
    attn_kernel<<<agrid, 256, attn_smem>>>(out);
}

// round 3
// speedup vs baseline: 1.5360x; 1.5360x over previous
#include <cuda_runtime.h>

#define BB 16
#define SS 2048
#define EE 512
#define HH 64
#define MROWS (BB*SS)   // 32768

// Scratch (allocation-free rule: __device__ globals)
__device__ float g_q[MROWS*HH];
__device__ float g_k[MROWS*HH];
__device__ float g_v[MROWS*HH];
__device__ int   g_seqlen[BB];
__device__ float g_sv[BB][HH];   // suffix sum of v over t >= Lpad
__device__ float g_tv[BB][HH];   // total sum of v over all t

// ---------------------------------------------------------------------------
// seq_lengths may arrive as int32 or int64 (JAX x64 off -> int32). Detect.
// ---------------------------------------------------------------------------
__global__ void normalize_seqlen_kernel(const int* __restrict__ raw)
{
    if (threadIdx.x != 0 || blockIdx.x != 0) return;
    bool looks64 = true;
    #pragma unroll
    for (int i = 0; i < 8; ++i) {
        int lo = raw[2 * i], hi = raw[2 * i + 1];
        if (hi != 0 || lo < 0 || lo > SS) looks64 = false;
    }
    #pragma unroll
    for (int b = 0; b < BB; ++b) {
        int v = looks64 ? raw[2 * b] : raw[b];
        if (v < 0) v = 0;
        if (v > SS) v = SS;
        g_seqlen[b] = v;
    }
}

// ---------------------------------------------------------------------------
// Projection: out = input @ W  (M=32768, K=512, N=64), masked for q,k.
// Skips q/k row-blocks entirely beyond Lpad (never read downstream).
// grid (512, 3), block 256. BM=64, BN=64, BK=16, 4x4 microtile/thread.
// ---------------------------------------------------------------------------
__global__ __launch_bounds__(256) void proj_kernel(
    const float* __restrict__ input,
    const float* __restrict__ Wq,
    const float* __restrict__ Wk,
    const float* __restrict__ Wv)
{
    const int w = blockIdx.y;                       // 0:q 1:k 2:v
    const int row0 = blockIdx.x * 64;
    const int batch = row0 >> 11;
    const int rin   = row0 & 2047;

    const int L    = g_seqlen[batch];
    const int Lpad = (L + 63) & ~63;
    if (w < 2 && rin >= Lpad) return;   // block never read downstream

    const float* __restrict__ W = (w == 0) ? Wq : (w == 1) ? Wk : Wv;
    float* __restrict__ out = (w == 0) ? g_q : (w == 1) ? g_k : g_v;

    __shared__ float As[16][65];   // A^T tile: [k][m], padded
    __shared__ float Bs[16][64];   // B tile: [k][n]

    const int tid = threadIdx.x;
    const int tx = tid & 15;          // n-group
    const int ty = tid >> 4;          // m-group
    const int tx4 = tx * 4, ty4 = ty * 4;

    const int ar  = tid >> 2;         // 0..63  (A tile row)
    const int ac4 = tid & 3;          // 0..3   (A tile col/4)
    const int br  = tid >> 4;         // 0..15  (B tile row)
    const int bc4 = tid & 15;         // 0..15  (B tile col/4)

    float c[4][4] = {};

    for (int k0 = 0; k0 < EE; k0 += 16) {
        float4 av = *reinterpret_cast<const float4*>(
            &input[(size_t)(row0 + ar) * EE + k0 + ac4 * 4]);
        As[ac4 * 4 + 0][ar] = av.x;
        As[ac4 * 4 + 1][ar] = av.y;
        As[ac4 * 4 + 2][ar] = av.z;
        As[ac4 * 4 + 3][ar] = av.w;

        *reinterpret_cast<float4*>(&Bs[br][bc4 * 4]) =
            *reinterpret_cast<const float4*>(&W[(size_t)(k0 + br) * HH + bc4 * 4]);
        __syncthreads();

        #pragma unroll
        for (int kk = 0; kk < 16; ++kk) {
            float a0 = As[kk][ty4 + 0];
            float a1 = As[kk][ty4 + 1];
            float a2 = As[kk][ty4 + 2];
            float a3 = As[kk][ty4 + 3];
            float4 b = *reinterpret_cast<const float4*>(&Bs[kk][tx4]);
            c[0][0] += a0 * b.x; c[0][1] += a0 * b.y; c[0][2] += a0 * b.z; c[0][3] += a0 * b.w;
            c[1][0] += a1 * b.x; c[1][1] += a1 * b.y; c[1][2] += a1 * b.z; c[1][3] += a1 * b.w;
            c[2][0] += a2 * b.x; c[2][1] += a2 * b.y; c[2][2] += a2 * b.z; c[2][3] += a2 * b.w;
            c[3][0] += a3 * b.x; c[3][1] += a3 * b.y; c[3][2] += a3 * b.z; c[3][3] += a3 * b.w;
        }
        __syncthreads();
    }

    #pragma unroll
    for (int i = 0; i < 4; ++i) {
        int s = rin + ty4 + i;
        bool z = (w < 2) && (s >= L);
        float4 v;
        v.x = z ? 0.f : c[i][0];
        v.y = z ? 0.f : c[i][1];
        v.z = z ? 0.f : c[i][2];
        v.w = z ? 0.f : c[i][3];
        *reinterpret_cast<float4*>(&out[(size_t)(row0 + ty4 + i) * HH + tx4]) = v;
    }
}

// ---------------------------------------------------------------------------
// Per-batch V sums: g_tv = sum over all t, g_sv = sum over t >= Lpad.
// grid 16, block 256 (4 groups x 64 cols, coalesced).
// ---------------------------------------------------------------------------
__global__ __launch_bounds__(256) void sumv_kernel()
{
    __shared__ float st[4][64];
    __shared__ float ss[4][64];
    const int b   = blockIdx.x;
    const int col = threadIdx.x & 63;
    const int grp = threadIdx.x >> 6;
    const int L    = g_seqlen[b];
    const int Lpad = (L + 63) & ~63;
    const float* __restrict__ vg = g_v + (size_t)b * SS * HH;

    float tot = 0.f, suf = 0.f;
    for (int t = grp; t < SS; t += 4) {
        float x = vg[(size_t)t * HH + col];
        tot += x;
        if (t >= Lpad) suf += x;
    }
    st[grp][col] = tot;
    ss[grp][col] = suf;
    __syncthreads();
    if (grp == 0) {
        g_tv[b][col] = st[0][col] + st[1][col] + st[2][col] + st[3][col];
        g_sv[b][col] = ss[0][col] + ss[1][col] + ss[2][col] + ss[3][col];
    }
}

// ---------------------------------------------------------------------------
// Flash attention over t < Lpad only. Padded columns (t >= Lpad) contribute
// exactly exp(-m) each to l and exp(-m)*suffix_sum(V) to o — folded into the
// initial state (m=0, l=2048-Lpad, o=g_sv). q-tiles beyond Lpad output mean(V).
// grid (32, 16), block 256.
// ---------------------------------------------------------------------------
__global__ __launch_bounds__(256) void attn_kernel(float* __restrict__ out)
{
    extern __shared__ float sm[];
    float* Qs = sm;                  // [64][64] natural [r][h], pre-scaled
    float* Ks = Qs + 64 * 64;        // [64][65] transposed [h][t]; reused as Ps [t][r]
    float* Vs = Ks + 64 * 65;        // [64][64] natural [t][h]

    const int b  = blockIdx.y;
    const int q0 = blockIdx.x * 64;
    const int L    = g_seqlen[b];
    const int Lpad = (L + 63) & ~63;

    const int tid = threadIdx.x;
    const int lc4 = tid & 15;
    const int lrb = (tid >> 4) * 4;

    // Fast path: q rows all zero -> uniform weights -> mean of all V rows.
    if (q0 >= Lpad) {
        float4 tv = *reinterpret_cast<const float4*>(&g_tv[b][lc4 * 4]);
        float4 mv;
        mv.x = tv.x * (1.0f / SS); mv.y = tv.y * (1.0f / SS);
        mv.z = tv.z * (1.0f / SS); mv.w = tv.w * (1.0f / SS);
        #pragma unroll
        for (int u = 0; u < 4; ++u)
            *reinterpret_cast<float4*>(
                &out[((size_t)b * SS + q0 + lrb + u) * HH + lc4 * 4]) = mv;
        return;
    }

    const float* __restrict__ qg = g_q + (size_t)b * SS * HH;
    const float* __restrict__ kg = g_k + (size_t)b * SS * HH;
    const float* __restrict__ vg = g_v + (size_t)b * SS * HH;

    const int tx = tid & 15, ty = tid >> 4;
    const int tx4 = tx * 4, ty4 = ty * 4;

    // Load Q tile (scaled by 1/sqrt(64) = 0.125)
    #pragma unroll
    for (int u = 0; u < 4; ++u) {
        float4 qv = *reinterpret_cast<const float4*>(
            &qg[(size_t)(q0 + lrb + u) * HH + lc4 * 4]);
        qv.x *= 0.125f; qv.y *= 0.125f; qv.z *= 0.125f; qv.w *= 0.125f;
        *reinterpret_cast<float4*>(&Qs[(lrb + u) * 64 + lc4 * 4]) = qv;
    }

    // Init state with the analytic contribution of padded columns.
    float4 svv = *reinterpret_cast<const float4*>(&g_sv[b][tx4]);
    float m[4], l[4], o[4][4];
    #pragma unroll
    for (int i = 0; i < 4; ++i) {
        m[i] = 0.0f;
        l[i] = (float)(SS - Lpad);
        o[i][0] = svv.x; o[i][1] = svv.y; o[i][2] = svv.z; o[i][3] = svv.w;
    }

    for (int t0 = 0; t0 < Lpad; t0 += 64) {
        __syncthreads();   // prev O-GEMM done before K/V overwrite
        #pragma unroll
        for (int u = 0; u < 4; ++u) {
            int t = lrb + u;
            float4 kv = *reinterpret_cast<const float4*>(
                &kg[(size_t)(t0 + t) * HH + lc4 * 4]);
            Ks[(lc4 * 4 + 0) * 65 + t] = kv.x;
            Ks[(lc4 * 4 + 1) * 65 + t] = kv.y;
            Ks[(lc4 * 4 + 2) * 65 + t] = kv.z;
            Ks[(lc4 * 4 + 3) * 65 + t] = kv.w;
            *reinterpret_cast<float4*>(&Vs[t * 64 + lc4 * 4]) =
                *reinterpret_cast<const float4*>(&vg[(size_t)(t0 + t) * HH + lc4 * 4]);
        }
        __syncthreads();

        // S = Q K^T
        float sacc[4][4] = {};
        #pragma unroll
        for (int h = 0; h < 64; ++h) {
            float a0 = Qs[(ty4 + 0) * 64 + h];
            float a1 = Qs[(ty4 + 1) * 64 + h];
            float a2 = Qs[(ty4 + 2) * 64 + h];
            float a3 = Qs[(ty4 + 3) * 64 + h];
            float b0 = Ks[h * 65 + tx4 + 0];
            float b1 = Ks[h * 65 + tx4 + 1];
            float b2 = Ks[h * 65 + tx4 + 2];
            float b3 = Ks[h * 65 + tx4 + 3];
            sacc[0][0] += a0 * b0; sacc[0][1] += a0 * b1; sacc[0][2] += a0 * b2; sacc[0][3] += a0 * b3;
            sacc[1][0] += a1 * b0; sacc[1][1] += a1 * b1; sacc[1][2] += a1 * b2; sacc[1][3] += a1 * b3;
            sacc[2][0] += a2 * b0; sacc[2][1] += a2 * b1; sacc[2][2] += a2 * b2; sacc[2][3] += a2 * b3;
            sacc[3][0] += a3 * b0; sacc[3][1] += a3 * b1; sacc[3][2] += a3 * b2; sacc[3][3] += a3 * b3;
        }

        // Online softmax per row (16-lane groups within each half-warp)
        #pragma unroll
        for (int i = 0; i < 4; ++i) {
            float mt = fmaxf(fmaxf(sacc[i][0], sacc[i][1]), fmaxf(sacc[i][2], sacc[i][3]));
            #pragma unroll
            for (int off = 8; off >= 1; off >>= 1)
                mt = fmaxf(mt, __shfl_xor_sync(0xffffffffu, mt, off));
            float mnew = fmaxf(m[i], mt);
            float alpha = __expf(m[i] - mnew);
            m[i] = mnew;
            float ssum = 0.f;
            #pragma unroll
            for (int j = 0; j < 4; ++j) {
                sacc[i][j] = __expf(sacc[i][j] - mnew);
                ssum += sacc[i][j];
            }
            #pragma unroll
            for (int off = 8; off >= 1; off >>= 1)
                ssum += __shfl_xor_sync(0xffffffffu, ssum, off);
            l[i] = l[i] * alpha + ssum;
            o[i][0] *= alpha; o[i][1] *= alpha; o[i][2] *= alpha; o[i][3] *= alpha;
        }

        __syncthreads();   // all S-GEMM reads of Ks done
        // Write P transposed into Ks buffer: Ps[t][r]
        #pragma unroll
        for (int i = 0; i < 4; ++i)
            #pragma unroll
            for (int j = 0; j < 4; ++j)
                Ks[(tx4 + j) * 65 + ty4 + i] = sacc[i][j];
        __syncthreads();

        // O += P @ V
        #pragma unroll
        for (int t = 0; t < 64; ++t) {
            float a0 = Ks[t * 65 + ty4 + 0];
            float a1 = Ks[t * 65 + ty4 + 1];
            float a2 = Ks[t * 65 + ty4 + 2];
            float a3 = Ks[t * 65 + ty4 + 3];
            float4 bv = *reinterpret_cast<const float4*>(&Vs[t * 64 + tx4]);
            o[0][0] += a0 * bv.x; o[0][1] += a0 * bv.y; o[0][2] += a0 * bv.z; o[0][3] += a0 * bv.w;
            o[1][0] += a1 * bv.x; o[1][1] += a1 * bv.y; o[1][2] += a1 * bv.z; o[1][3] += a1 * bv.w;
            o[2][0] += a2 * bv.x; o[2][1] += a2 * bv.y; o[2][2] += a2 * bv.z; o[2][3] += a2 * bv.w;
            o[3][0] += a3 * bv.x; o[3][1] += a3 * bv.y; o[3][2] += a3 * bv.z; o[3][3] += a3 * bv.w;
        }
    }

    // Epilogue: normalize and store (l >= 2048 - Lpad + ... > 0 always)
    #pragma unroll
    for (int i = 0; i < 4; ++i) {
        float inv = 1.0f / l[i];
        float4 ov;
        ov.x = o[i][0] * inv; ov.y = o[i][1] * inv;
        ov.z = o[i][2] * inv; ov.w = o[i][3] * inv;
        *reinterpret_cast<float4*>(
            &out[((size_t)b * SS + q0 + ty4 + i) * HH + tx4]) = ov;
    }
}

// ---------------------------------------------------------------------------
extern "C" void kernel_launch(void* const* d_in, const int* in_sizes, int n_in,
                              void* d_out, int out_size)
{
    const float* input  = (const float*)d_in[0];
    const int*   seqraw = (const int*)d_in[1];
    const float* Wq     = (const float*)d_in[2];
    const float* Wk     = (const float*)d_in[3];
    const float* Wv     = (const float*)d_in[4];
    float*       out    = (float*)d_out;

    const int attn_smem = (64 * 64 + 64 * 65 + 64 * 64) * (int)sizeof(float); // 49408
    cudaFuncSetAttribute(attn_kernel,
                         cudaFuncAttributeMaxDynamicSharedMemorySize, attn_smem);

    normalize_seqlen_kernel<<<1, 32>>>(seqraw);

    dim3 pgrid(MROWS / 64, 3);
    proj_kernel<<<pgrid, 256>>>(input, Wq, Wk, Wv);

    sumv_kernel<<<BB, 256>>>();

    dim3 agrid(SS / 64, BB);
    attn_kernel<<<agrid, 256, attn_smem>>>(out);
}

// round 4
// speedup vs baseline: 2.4200x; 1.5755x over previous
#include <cuda_runtime.h>
#include <cstdint>

#define BB 16
#define SS 2048
#define EE 512
#define HH 64
#define MROWS (BB*SS)   // 32768
#define PAD 68          // smem row stride (floats): banks 4g+t -> conflict-free frags

// Scratch (allocation-free rule: __device__ globals)
__device__ float g_q[MROWS*HH];
__device__ float g_k[MROWS*HH];
__device__ float g_v[MROWS*HH];
__device__ int   g_seqlen[BB];
__device__ float g_sv[BB][HH];   // suffix sum of v over t >= Lpad
__device__ float g_tv[BB][HH];   // total sum of v over all t

__device__ __forceinline__ uint32_t f2tf32(float x) {
    uint32_t u;
    asm("cvt.rna.tf32.f32 %0, %1;" : "=r"(u) : "f"(x));
    return u;
}

__device__ __forceinline__ void mma_tf32(float d[4], uint32_t a0, uint32_t a1,
                                         uint32_t a2, uint32_t a3,
                                         uint32_t b0, uint32_t b1) {
    asm volatile(
        "mma.sync.aligned.m16n8k8.row.col.f32.tf32.tf32.f32 "
        "{%0,%1,%2,%3}, {%4,%5,%6,%7}, {%8,%9}, {%0,%1,%2,%3};"
        : "+f"(d[0]), "+f"(d[1]), "+f"(d[2]), "+f"(d[3])
        : "r"(a0), "r"(a1), "r"(a2), "r"(a3), "r"(b0), "r"(b1));
}

// ---------------------------------------------------------------------------
// seq_lengths may arrive as int32 or int64 (JAX x64 off -> int32). Detect.
// ---------------------------------------------------------------------------
__global__ void normalize_seqlen_kernel(const int* __restrict__ raw)
{
    if (threadIdx.x != 0 || blockIdx.x != 0) return;
    bool looks64 = true;
    #pragma unroll
    for (int i = 0; i < 8; ++i) {
        int lo = raw[2 * i], hi = raw[2 * i + 1];
        if (hi != 0 || lo < 0 || lo > SS) looks64 = false;
    }
    #pragma unroll
    for (int b = 0; b < BB; ++b) {
        int v = looks64 ? raw[2 * b] : raw[b];
        if (v < 0) v = 0;
        if (v > SS) v = SS;
        g_seqlen[b] = v;
    }
}

// ---------------------------------------------------------------------------
// Projection: out = input @ W  (M=32768, K=512, N=64), masked for q,k.
// Skips q/k row-blocks entirely beyond Lpad (never read downstream).
// ---------------------------------------------------------------------------
__global__ __launch_bounds__(256) void proj_kernel(
    const float* __restrict__ input,
    const float* __restrict__ Wq,
    const float* __restrict__ Wk,
    const float* __restrict__ Wv)
{
    const int w = blockIdx.y;                       // 0:q 1:k 2:v
    const int row0 = blockIdx.x * 64;
    const int batch = row0 >> 11;
    const int rin   = row0 & 2047;

    const int L    = g_seqlen[batch];
    const int Lpad = (L + 63) & ~63;
    if (w < 2 && rin >= Lpad) return;   // block never read downstream

    const float* __restrict__ W = (w == 0) ? Wq : (w == 1) ? Wk : Wv;
    float* __restrict__ out = (w == 0) ? g_q : (w == 1) ? g_k : g_v;

    __shared__ float As[16][65];   // A^T tile: [k][m], padded
    __shared__ float Bs[16][64];   // B tile: [k][n]

    const int tid = threadIdx.x;
    const int tx = tid & 15;
    const int ty = tid >> 4;
    const int tx4 = tx * 4, ty4 = ty * 4;

    const int ar  = tid >> 2;
    const int ac4 = tid & 3;
    const int br  = tid >> 4;
    const int bc4 = tid & 15;

    float c[4][4] = {};

    for (int k0 = 0; k0 < EE; k0 += 16) {
        float4 av = *reinterpret_cast<const float4*>(
            &input[(size_t)(row0 + ar) * EE + k0 + ac4 * 4]);
        As[ac4 * 4 + 0][ar] = av.x;
        As[ac4 * 4 + 1][ar] = av.y;
        As[ac4 * 4 + 2][ar] = av.z;
        As[ac4 * 4 + 3][ar] = av.w;

        *reinterpret_cast<float4*>(&Bs[br][bc4 * 4]) =
            *reinterpret_cast<const float4*>(&W[(size_t)(k0 + br) * HH + bc4 * 4]);
        __syncthreads();

        #pragma unroll
        for (int kk = 0; kk < 16; ++kk) {
            float a0 = As[kk][ty4 + 0];
            float a1 = As[kk][ty4 + 1];
            float a2 = As[kk][ty4 + 2];
            float a3 = As[kk][ty4 + 3];
            float4 b = *reinterpret_cast<const float4*>(&Bs[kk][tx4]);
            c[0][0] += a0 * b.x; c[0][1] += a0 * b.y; c[0][2] += a0 * b.z; c[0][3] += a0 * b.w;
            c[1][0] += a1 * b.x; c[1][1] += a1 * b.y; c[1][2] += a1 * b.z; c[1][3] += a1 * b.w;
            c[2][0] += a2 * b.x; c[2][1] += a2 * b.y; c[2][2] += a2 * b.z; c[2][3] += a2 * b.w;
            c[3][0] += a3 * b.x; c[3][1] += a3 * b.y; c[3][2] += a3 * b.z; c[3][3] += a3 * b.w;
        }
        __syncthreads();
    }

    #pragma unroll
    for (int i = 0; i < 4; ++i) {
        int s = rin + ty4 + i;
        bool z = (w < 2) && (s >= L);
        float4 v;
        v.x = z ? 0.f : c[i][0];
        v.y = z ? 0.f : c[i][1];
        v.z = z ? 0.f : c[i][2];
        v.w = z ? 0.f : c[i][3];
        *reinterpret_cast<float4*>(&out[(size_t)(row0 + ty4 + i) * HH + tx4]) = v;
    }
}

// ---------------------------------------------------------------------------
// Per-batch V sums: g_tv = sum over all t, g_sv = sum over t >= Lpad.
// ---------------------------------------------------------------------------
__global__ __launch_bounds__(256) void sumv_kernel()
{
    __shared__ float st[4][64];
    __shared__ float ss[4][64];
    const int b   = blockIdx.x;
    const int col = threadIdx.x & 63;
    const int grp = threadIdx.x >> 6;
    const int L    = g_seqlen[b];
    const int Lpad = (L + 63) & ~63;
    const float* __restrict__ vg = g_v + (size_t)b * SS * HH;

    float tot = 0.f, suf = 0.f;
    for (int t = grp; t < SS; t += 4) {
        float x = vg[(size_t)t * HH + col];
        tot += x;
        if (t >= Lpad) suf += x;
    }
    st[grp][col] = tot;
    ss[grp][col] = suf;
    __syncthreads();
    if (grp == 0) {
        g_tv[b][col] = st[0][col] + st[1][col] + st[2][col] + st[3][col];
        g_sv[b][col] = ss[0][col] + ss[1][col] + ss[2][col] + ss[3][col];
    }
}

// ---------------------------------------------------------------------------
// Flash attention, tf32 tensor-core version.
// 64 q-rows x 64-key tiles, 128 threads = 4 warps, warp w owns rows 16w..16w+15.
// Q pre-scaled by 0.125*log2(e); softmax in log2 domain via exp2f.
// Padded columns (t >= Lpad) folded analytically into the initial state.
// Smem: Qs[64][68] (P overlaid after S-reads), Ks[64][68], Vs[64][68], tf32 bits.
// ---------------------------------------------------------------------------
__global__ __launch_bounds__(128) void attn_kernel(float* __restrict__ out)
{
    extern __shared__ uint32_t sm[];
    uint32_t* Qs = sm;               // [64][PAD] tf32 Q (pre-scaled)
    uint32_t* Ks = Qs + 64 * PAD;    // [64][PAD] tf32 K natural [key][h]; P overlay
    uint32_t* Vs = Ks + 64 * PAD;    // [64][PAD] tf32 V natural [key][h]

    const int b  = blockIdx.y;
    const int q0 = blockIdx.x * 64;
    const int L    = g_seqlen[b];
    const int Lpad = (L + 63) & ~63;

    const int tid  = threadIdx.x;
    const int warp = tid >> 5;
    const int lane = tid & 31;
    const int g    = lane >> 2;      // group id 0..7
    const int t    = lane & 3;       // thread-in-group 0..3
    const int mrow = warp * 16 + g;  // this thread's low row within the 64-row tile

    // Fast path: q rows all zero -> uniform weights -> mean of all V rows.
    if (q0 >= Lpad) {
        const int c4 = tid & 15;
        const int rb = (tid >> 4) * 8;
        float4 tv = *reinterpret_cast<const float4*>(&g_tv[b][c4 * 4]);
        float4 mv;
        mv.x = tv.x * (1.0f / SS); mv.y = tv.y * (1.0f / SS);
        mv.z = tv.z * (1.0f / SS); mv.w = tv.w * (1.0f / SS);
        #pragma unroll
        for (int u = 0; u < 8; ++u)
            *reinterpret_cast<float4*>(
                &out[((size_t)b * SS + q0 + rb + u) * HH + c4 * 4]) = mv;
        return;
    }

    const float* __restrict__ qg = g_q + (size_t)b * SS * HH;
    const float* __restrict__ kg = g_k + (size_t)b * SS * HH;
    const float* __restrict__ vg = g_v + (size_t)b * SS * HH;

    // Prologue: Q tile -> smem, scaled by 0.125 * log2(e), tf32.
    const float qscale = 0.125f * 1.4426950408889634f;
    #pragma unroll
    for (int i = 0; i < 8; ++i) {
        int lin = tid + 128 * i;        // 0..1023
        int r = lin >> 4, c4 = lin & 15;
        float4 qv = *reinterpret_cast<const float4*>(
            &qg[(size_t)(q0 + r) * HH + c4 * 4]);
        uint4 u;
        u.x = f2tf32(qv.x * qscale); u.y = f2tf32(qv.y * qscale);
        u.z = f2tf32(qv.z * qscale); u.w = f2tf32(qv.w * qscale);
        *reinterpret_cast<uint4*>(&Qs[r * PAD + c4 * 4]) = u;
    }

    // State: m/l for rows mrow (idx 0) and mrow+8 (idx 1); O acc per h-ntile.
    float m0 = 0.f, m1 = 0.f;
    float l0 = (float)(SS - Lpad), l1 = l0;
    float oacc[8][4];
    #pragma unroll
    for (int n = 0; n < 8; ++n) {
        float2 s2 = *reinterpret_cast<const float2*>(&g_sv[b][n * 8 + 2 * t]);
        oacc[n][0] = s2.x; oacc[n][1] = s2.y;   // row mrow
        oacc[n][2] = s2.x; oacc[n][3] = s2.y;   // row mrow+8 (same columns)
    }

    for (int t0 = 0; t0 < Lpad; t0 += 64) {
        __syncthreads();   // prev iter's K/V/P reads done
        // Fill K and V tiles (natural [key][h], tf32)
        #pragma unroll
        for (int i = 0; i < 8; ++i) {
            int lin = tid + 128 * i;
            int r = lin >> 4, c4 = lin & 15;
            float4 kv = *reinterpret_cast<const float4*>(
                &kg[(size_t)(t0 + r) * HH + c4 * 4]);
            uint4 uk;
            uk.x = f2tf32(kv.x); uk.y = f2tf32(kv.y);
            uk.z = f2tf32(kv.z); uk.w = f2tf32(kv.w);
            *reinterpret_cast<uint4*>(&Ks[r * PAD + c4 * 4]) = uk;
            float4 vv = *reinterpret_cast<const float4*>(
                &vg[(size_t)(t0 + r) * HH + c4 * 4]);
            uint4 uv;
            uv.x = f2tf32(vv.x); uv.y = f2tf32(vv.y);
            uv.z = f2tf32(vv.z); uv.w = f2tf32(vv.w);
            *reinterpret_cast<uint4*>(&Vs[r * PAD + c4 * 4]) = uv;
        }
        __syncthreads();

        // S = Q K^T in log2-units. sacc[n] = m16n8 acc for key-cols n*8..n*8+7.
        float sacc[8][4];
        #pragma unroll
        for (int n = 0; n < 8; ++n)
            sacc[n][0] = sacc[n][1] = sacc[n][2] = sacc[n][3] = 0.f;
        #pragma unroll
        for (int k = 0; k < 8; ++k) {
            uint32_t a0 = Qs[mrow * PAD + k * 8 + t];
            uint32_t a1 = Qs[(mrow + 8) * PAD + k * 8 + t];
            uint32_t a2 = Qs[mrow * PAD + k * 8 + t + 4];
            uint32_t a3 = Qs[(mrow + 8) * PAD + k * 8 + t + 4];
            #pragma unroll
            for (int n = 0; n < 8; ++n) {
                uint32_t b0 = Ks[(n * 8 + g) * PAD + k * 8 + t];
                uint32_t b1 = Ks[(n * 8 + g) * PAD + k * 8 + t + 4];
                mma_tf32(sacc[n], a0, a1, a2, a3, b0, b1);
            }
        }

        // Online softmax (rows fully intra-warp; 4-lane butterfly reductions)
        float mx0 = sacc[0][0], mx1 = sacc[0][2];
        #pragma unroll
        for (int n = 0; n < 8; ++n) {
            mx0 = fmaxf(mx0, fmaxf(sacc[n][0], sacc[n][1]));
            mx1 = fmaxf(mx1, fmaxf(sacc[n][2], sacc[n][3]));
        }
        mx0 = fmaxf(mx0, __shfl_xor_sync(0xffffffffu, mx0, 1));
        mx0 = fmaxf(mx0, __shfl_xor_sync(0xffffffffu, mx0, 2));
        mx1 = fmaxf(mx1, __shfl_xor_sync(0xffffffffu, mx1, 1));
        mx1 = fmaxf(mx1, __shfl_xor_sync(0xffffffffu, mx1, 2));
        float mn0 = fmaxf(m0, mx0), mn1 = fmaxf(m1, mx1);
        float al0 = exp2f(m0 - mn0), al1 = exp2f(m1 - mn1);
        m0 = mn0; m1 = mn1;

        float rs0 = 0.f, rs1 = 0.f;
        #pragma unroll
        for (int n = 0; n < 8; ++n) {
            sacc[n][0] = exp2f(sacc[n][0] - mn0);
            sacc[n][1] = exp2f(sacc[n][1] - mn0);
            sacc[n][2] = exp2f(sacc[n][2] - mn1);
            sacc[n][3] = exp2f(sacc[n][3] - mn1);
            rs0 += sacc[n][0] + sacc[n][1];
            rs1 += sacc[n][2] + sacc[n][3];
        }
        rs0 += __shfl_xor_sync(0xffffffffu, rs0, 1);
        rs0 += __shfl_xor_sync(0xffffffffu, rs0, 2);
        rs1 += __shfl_xor_sync(0xffffffffu, rs1, 1);
        rs1 += __shfl_xor_sync(0xffffffffu, rs1, 2);
        l0 = l0 * al0 + rs0;
        l1 = l1 * al1 + rs1;
        #pragma unroll
        for (int n = 0; n < 8; ++n) {
            oacc[n][0] *= al0; oacc[n][1] *= al0;
            oacc[n][2] *= al1; oacc[n][3] *= al1;
        }

        __syncthreads();   // all warps finished reading Ks as keys
        // Write P (tf32) into Ks region: P[row][key], stride PAD. STS.64 pairs.
        #pragma unroll
        for (int n = 0; n < 8; ++n) {
            uint2 lo2 = make_uint2(f2tf32(sacc[n][0]), f2tf32(sacc[n][1]));
            uint2 hi2 = make_uint2(f2tf32(sacc[n][2]), f2tf32(sacc[n][3]));
            *reinterpret_cast<uint2*>(&Ks[mrow * PAD + n * 8 + 2 * t])       = lo2;
            *reinterpret_cast<uint2*>(&Ks[(mrow + 8) * PAD + n * 8 + 2 * t]) = hi2;
        }
        __syncwarp();      // P rows are private to this warp

        // O += P @ V. A = P (m16 x k8 keys), B = V (k8 keys x n8 h).
        #pragma unroll
        for (int k = 0; k < 8; ++k) {
            uint32_t a0 = Ks[mrow * PAD + k * 8 + t];
            uint32_t a1 = Ks[(mrow + 8) * PAD + k * 8 + t];
            uint32_t a2 = Ks[mrow * PAD + k * 8 + t + 4];
            uint32_t a3 = Ks[(mrow + 8) * PAD + k * 8 + t + 4];
            #pragma unroll
            for (int n = 0; n < 8; ++n) {
                uint32_t b0 = Vs[(k * 8 + t) * PAD + n * 8 + g];
                uint32_t b1 = Vs[(k * 8 + t + 4) * PAD + n * 8 + g];
                mma_tf32(oacc[n], a0, a1, a2, a3, b0, b1);
            }
        }
    }

    // Epilogue: normalize and store. Row mrow cols {8n+2t, 8n+2t+1}.
    float inv0 = 1.0f / l0, inv1 = 1.0f / l1;
    size_t base = ((size_t)b * SS + q0) * HH;
    #pragma unroll
    for (int n = 0; n < 8; ++n) {
        float2 lo = make_float2(oacc[n][0] * inv0, oacc[n][1] * inv0);
        float2 hi = make_float2(oacc[n][2] * inv1, oacc[n][3] * inv1);
        *reinterpret_cast<float2*>(&out[base + (size_t)mrow * HH + n * 8 + 2 * t])       = lo;
        *reinterpret_cast<float2*>(&out[base + (size_t)(mrow + 8) * HH + n * 8 + 2 * t]) = hi;
    }
}

// ---------------------------------------------------------------------------
extern "C" void kernel_launch(void* const* d_in, const int* in_sizes, int n_in,
                              void* d_out, int out_size)
{
    const float* input  = (const float*)d_in[0];
    const int*   seqraw = (const int*)d_in[1];
    const float* Wq     = (const float*)d_in[2];
    const float* Wk     = (const float*)d_in[3];
    const float* Wv     = (const float*)d_in[4];
    float*       out    = (float*)d_out;

    const int attn_smem = 3 * 64 * PAD * (int)sizeof(uint32_t); // 52224
    cudaFuncSetAttribute(attn_kernel,
                         cudaFuncAttributeMaxDynamicSharedMemorySize, attn_smem);

    normalize_seqlen_kernel<<<1, 32>>>(seqraw);

    dim3 pgrid(MROWS / 64, 3);
    proj_kernel<<<pgrid, 256>>>(input, Wq, Wk, Wv);

    sumv_kernel<<<BB, 256>>>();

    dim3 agrid(SS / 64, BB);
    attn_kernel<<<agrid, 128, attn_smem>>>(out);
}

// round 5
// speedup vs baseline: 3.6523x; 1.5092x over previous
#include <cuda_runtime.h>
#include <cstdint>

#define BB 16
#define SS 2048
#define EE 512
#define HH 64
#define MROWS (BB*SS)   // 32768
#define PAD 68          // smem row stride (uints): mma frag loads conflict-free

// Scratch (allocation-free rule: __device__ globals)
__device__ float    g_q[MROWS*HH];
__device__ float    g_k[MROWS*HH];
__device__ float    g_v[MROWS*HH];
__device__ int      g_seqlen[BB];
__device__ int      g_sched[512];          // attn work schedule: b*32 + qtile
__device__ float    g_sv[BB][HH];          // suffix sum of v over t >= Lpad
__device__ float    g_tv[BB][HH];          // total sum of v over all t
__device__ uint32_t g_wt[3][HH][EE];       // W transposed, tf32: [w][n][k]

__device__ __forceinline__ uint32_t f2tf32(float x) {
    uint32_t u;
    asm("cvt.rna.tf32.f32 %0, %1;" : "=r"(u) : "f"(x));
    return u;
}

__device__ __forceinline__ void mma_tf32(float d[4], uint32_t a0, uint32_t a1,
                                         uint32_t a2, uint32_t a3,
                                         uint32_t b0, uint32_t b1) {
    asm volatile(
        "mma.sync.aligned.m16n8k8.row.col.f32.tf32.tf32.f32 "
        "{%0,%1,%2,%3}, {%4,%5,%6,%7}, {%8,%9}, {%0,%1,%2,%3};"
        : "+f"(d[0]), "+f"(d[1]), "+f"(d[2]), "+f"(d[3])
        : "r"(a0), "r"(a1), "r"(a2), "r"(a3), "r"(b0), "r"(b1));
}

// ---------------------------------------------------------------------------
// seq_lengths int32/int64 detection + build the attn schedule:
// real (b,qtile) units sorted by descending Lpad first, fast-path tiles last.
// ---------------------------------------------------------------------------
__global__ void normalize_seqlen_kernel(const int* __restrict__ raw)
{
    if (threadIdx.x != 0 || blockIdx.x != 0) return;
    bool looks64 = true;
    #pragma unroll
    for (int i = 0; i < 8; ++i) {
        int lo = raw[2 * i], hi = raw[2 * i + 1];
        if (hi != 0 || lo < 0 || lo > SS) looks64 = false;
    }
    int L[BB];
    #pragma unroll
    for (int b = 0; b < BB; ++b) {
        int v = looks64 ? raw[2 * b] : raw[b];
        if (v < 0) v = 0;
        if (v > SS) v = SS;
        g_seqlen[b] = v;
        L[b] = v;
    }
    // insertion sort batch ids by Lpad desc
    int ord[BB];
    #pragma unroll
    for (int b = 0; b < BB; ++b) ord[b] = b;
    for (int i = 1; i < BB; ++i) {
        int key = ord[i];
        int kl = (L[key] + 63) & ~63;
        int j = i - 1;
        while (j >= 0 && ((L[ord[j]] + 63) & ~63) < kl) {
            ord[j + 1] = ord[j];
            --j;
        }
        ord[j + 1] = key;
    }
    int pos = 0;
    for (int i = 0; i < BB; ++i) {
        int b = ord[i];
        int nq = ((L[b] + 63) & ~63) >> 6;
        for (int qt = 0; qt < nq; ++qt) g_sched[pos++] = b * 32 + qt;
    }
    for (int i = 0; i < BB; ++i) {
        int b = ord[i];
        int nq = ((L[b] + 63) & ~63) >> 6;
        for (int qt = nq; qt < 32; ++qt) g_sched[pos++] = b * 32 + qt;
    }
}

// ---------------------------------------------------------------------------
// W transpose + tf32 convert: g_wt[w][n][k] = tf32(W[k][n]).
// grid 384 x 256 threads.
// ---------------------------------------------------------------------------
__global__ __launch_bounds__(256) void prep_w_kernel(
    const float* __restrict__ Wq,
    const float* __restrict__ Wk,
    const float* __restrict__ Wv)
{
    int idx = blockIdx.x * 256 + threadIdx.x;      // 0 .. 3*32768-1
    int w = idx >> 15;
    int rem = idx & 32767;
    int k = rem >> 6;
    int n = rem & 63;
    const float* W = (w == 0) ? Wq : (w == 1) ? Wk : Wv;
    g_wt[w][n][k] = f2tf32(W[k * HH + n]);
}

// ---------------------------------------------------------------------------
// Projection via tf32 mma with hi/lo input split (fp32-grade accuracy in A).
// out = input @ W, M=32768 N=64 K=512. grid (512,3), 128 threads / 4 warps.
// Each warp: rows mrow..mrow+15 of the 64-row block, all 64 cols.
// q/k blocks beyond Lpad skipped (never read downstream). q/k rows >= L zeroed.
// ---------------------------------------------------------------------------
__global__ __launch_bounds__(128) void proj_kernel(const float* __restrict__ input)
{
    const int w    = blockIdx.y;                   // 0:q 1:k 2:v
    const int row0 = blockIdx.x * 64;
    const int batch = row0 >> 11;
    const int rin   = row0 & 2047;

    const int L    = g_seqlen[batch];
    const int Lpad = (L + 63) & ~63;
    if (w < 2 && rin >= Lpad) return;

    float* __restrict__ out = (w == 0) ? g_q : (w == 1) ? g_k : g_v;

    extern __shared__ uint32_t sm[];
    uint32_t* Ah = sm;                 // [64][PAD] tf32 hi(input)
    uint32_t* Al = Ah + 64 * PAD;      // [64][PAD] tf32 lo(input)
    uint32_t* Bs = Al + 64 * PAD;      // [64][PAD] tf32 W^T chunk: [n][kk]

    const int tid  = threadIdx.x;
    const int warp = tid >> 5;
    const int lane = tid & 31;
    const int g    = lane >> 2;
    const int t    = lane & 3;
    const int mrow = warp * 16 + g;

    float acc[8][4];
    #pragma unroll
    for (int n = 0; n < 8; ++n)
        acc[n][0] = acc[n][1] = acc[n][2] = acc[n][3] = 0.f;

    for (int c = 0; c < 8; ++c) {      // k0 = c*64
        __syncthreads();
        // Fill A hi/lo (64 x 64 fp32 chunk)
        #pragma unroll
        for (int i = 0; i < 8; ++i) {
            int lin = tid + 128 * i;
            int r = lin >> 4, c4 = lin & 15;
            float4 av = *reinterpret_cast<const float4*>(
                &input[(size_t)(row0 + r) * EE + c * 64 + c4 * 4]);
            uint4 uh, ul;
            uh.x = f2tf32(av.x); ul.x = f2tf32(av.x - __uint_as_float(uh.x));
            uh.y = f2tf32(av.y); ul.y = f2tf32(av.y - __uint_as_float(uh.y));
            uh.z = f2tf32(av.z); ul.z = f2tf32(av.z - __uint_as_float(uh.z));
            uh.w = f2tf32(av.w); ul.w = f2tf32(av.w - __uint_as_float(uh.w));
            *reinterpret_cast<uint4*>(&Ah[r * PAD + c4 * 4]) = uh;
            *reinterpret_cast<uint4*>(&Al[r * PAD + c4 * 4]) = ul;
        }
        // Fill B chunk: Bs[n][kk] = g_wt[w][n][c*64+kk] (pure copy, coalesced)
        #pragma unroll
        for (int i = 0; i < 8; ++i) {
            int lin = tid + 128 * i;
            int n = lin >> 4, k4 = lin & 15;
            *reinterpret_cast<uint4*>(&Bs[n * PAD + k4 * 4]) =
                *reinterpret_cast<const uint4*>(&g_wt[w][n][c * 64 + k4 * 4]);
        }
        __syncthreads();

        #pragma unroll
        for (int k = 0; k < 8; ++k) {
            uint32_t ah0 = Ah[mrow * PAD + k * 8 + t];
            uint32_t ah1 = Ah[(mrow + 8) * PAD + k * 8 + t];
            uint32_t ah2 = Ah[mrow * PAD + k * 8 + t + 4];
            uint32_t ah3 = Ah[(mrow + 8) * PAD + k * 8 + t + 4];
            uint32_t al0 = Al[mrow * PAD + k * 8 + t];
            uint32_t al1 = Al[(mrow + 8) * PAD + k * 8 + t];
            uint32_t al2 = Al[mrow * PAD + k * 8 + t + 4];
            uint32_t al3 = Al[(mrow + 8) * PAD + k * 8 + t + 4];
            #pragma unroll
            for (int n = 0; n < 8; ++n) {
                uint32_t b0 = Bs[(n * 8 + g) * PAD + k * 8 + t];
                uint32_t b1 = Bs[(n * 8 + g) * PAD + k * 8 + t + 4];
                mma_tf32(acc[n], ah0, ah1, ah2, ah3, b0, b1);
                mma_tf32(acc[n], al0, al1, al2, al3, b0, b1);
            }
        }
    }

    // Epilogue: m16n8 layout -> row mrow cols {8n+2t,8n+2t+1}; mask q/k rows >= L.
    bool z0 = (w < 2) && (rin + mrow >= L);
    bool z1 = (w < 2) && (rin + mrow + 8 >= L);
    size_t base = (size_t)row0 * HH;
    #pragma unroll
    for (int n = 0; n < 8; ++n) {
        float2 lo = z0 ? make_float2(0.f, 0.f) : make_float2(acc[n][0], acc[n][1]);
        float2 hi = z1 ? make_float2(0.f, 0.f) : make_float2(acc[n][2], acc[n][3]);
        *reinterpret_cast<float2*>(&out[base + (size_t)mrow * HH + n * 8 + 2 * t])       = lo;
        *reinterpret_cast<float2*>(&out[base + (size_t)(mrow + 8) * HH + n * 8 + 2 * t]) = hi;
    }
}

// ---------------------------------------------------------------------------
// Per-batch V sums: g_tv = sum over all t, g_sv = sum over t >= Lpad.
// ---------------------------------------------------------------------------
__global__ __launch_bounds__(256) void sumv_kernel()
{
    __shared__ float st[4][64];
    __shared__ float ss[4][64];
    const int b   = blockIdx.x;
    const int col = threadIdx.x & 63;
    const int grp = threadIdx.x >> 6;
    const int L    = g_seqlen[b];
    const int Lpad = (L + 63) & ~63;
    const float* __restrict__ vg = g_v + (size_t)b * SS * HH;

    float tot = 0.f, suf = 0.f;
    for (int t = grp; t < SS; t += 4) {
        float x = vg[(size_t)t * HH + col];
        tot += x;
        if (t >= Lpad) suf += x;
    }
    st[grp][col] = tot;
    ss[grp][col] = suf;
    __syncthreads();
    if (grp == 0) {
        g_tv[b][col] = st[0][col] + st[1][col] + st[2][col] + st[3][col];
        g_sv[b][col] = ss[0][col] + ss[1][col] + ss[2][col] + ss[3][col];
    }
}

// ---------------------------------------------------------------------------
// Flash attention, tf32 tensor cores, schedule-driven for load balance.
// 64 q-rows x 64-key tiles, 128 threads = 4 warps, warp owns 16 rows.
// Padded key columns folded analytically into initial state.
// ---------------------------------------------------------------------------
__global__ __launch_bounds__(128) void attn_kernel(float* __restrict__ out)
{
    extern __shared__ uint32_t sm[];
    uint32_t* Qs = sm;               // [64][PAD] tf32 Q (pre-scaled)
    uint32_t* Ks = Qs + 64 * PAD;    // [64][PAD] tf32 K natural [key][h]; P overlay
    uint32_t* Vs = Ks + 64 * PAD;    // [64][PAD] tf32 V natural [key][h]

    const int ent = g_sched[blockIdx.x];
    const int b   = ent >> 5;
    const int q0  = (ent & 31) * 64;
    const int L    = g_seqlen[b];
    const int Lpad = (L + 63) & ~63;

    const int tid  = threadIdx.x;
    const int warp = tid >> 5;
    const int lane = tid & 31;
    const int g    = lane >> 2;
    const int t    = lane & 3;
    const int mrow = warp * 16 + g;

    // Fast path: q rows all zero -> uniform weights -> mean of all V rows.
    if (q0 >= Lpad) {
        const int c4 = tid & 15;
        const int rb = (tid >> 4) * 8;
        float4 tv = *reinterpret_cast<const float4*>(&g_tv[b][c4 * 4]);
        float4 mv;
        mv.x = tv.x * (1.0f / SS); mv.y = tv.y * (1.0f / SS);
        mv.z = tv.z * (1.0f / SS); mv.w = tv.w * (1.0f / SS);
        #pragma unroll
        for (int u = 0; u < 8; ++u)
            *reinterpret_cast<float4*>(
                &out[((size_t)b * SS + q0 + rb + u) * HH + c4 * 4]) = mv;
        return;
    }

    const float* __restrict__ qg = g_q + (size_t)b * SS * HH;
    const float* __restrict__ kg = g_k + (size_t)b * SS * HH;
    const float* __restrict__ vg = g_v + (size_t)b * SS * HH;

    // Prologue: Q tile -> smem, scaled by 0.125 * log2(e), tf32.
    const float qscale = 0.125f * 1.4426950408889634f;
    #pragma unroll
    for (int i = 0; i < 8; ++i) {
        int lin = tid + 128 * i;
        int r = lin >> 4, c4 = lin & 15;
        float4 qv = *reinterpret_cast<const float4*>(
            &qg[(size_t)(q0 + r) * HH + c4 * 4]);
        uint4 u;
        u.x = f2tf32(qv.x * qscale); u.y = f2tf32(qv.y * qscale);
        u.z = f2tf32(qv.z * qscale); u.w = f2tf32(qv.w * qscale);
        *reinterpret_cast<uint4*>(&Qs[r * PAD + c4 * 4]) = u;
    }

    float m0 = 0.f, m1 = 0.f;
    float l0 = (float)(SS - Lpad), l1 = l0;
    float oacc[8][4];
    #pragma unroll
    for (int n = 0; n < 8; ++n) {
        float2 s2 = *reinterpret_cast<const float2*>(&g_sv[b][n * 8 + 2 * t]);
        oacc[n][0] = s2.x; oacc[n][1] = s2.y;
        oacc[n][2] = s2.x; oacc[n][3] = s2.y;
    }

    for (int t0 = 0; t0 < Lpad; t0 += 64) {
        __syncthreads();
        #pragma unroll
        for (int i = 0; i < 8; ++i) {
            int lin = tid + 128 * i;
            int r = lin >> 4, c4 = lin & 15;
            float4 kv = *reinterpret_cast<const float4*>(
                &kg[(size_t)(t0 + r) * HH + c4 * 4]);
            uint4 uk;
            uk.x = f2tf32(kv.x); uk.y = f2tf32(kv.y);
            uk.z = f2tf32(kv.z); uk.w = f2tf32(kv.w);
            *reinterpret_cast<uint4*>(&Ks[r * PAD + c4 * 4]) = uk;
            float4 vv = *reinterpret_cast<const float4*>(
                &vg[(size_t)(t0 + r) * HH + c4 * 4]);
            uint4 uv;
            uv.x = f2tf32(vv.x); uv.y = f2tf32(vv.y);
            uv.z = f2tf32(vv.z); uv.w = f2tf32(vv.w);
            *reinterpret_cast<uint4*>(&Vs[r * PAD + c4 * 4]) = uv;
        }
        __syncthreads();

        // S = Q K^T (log2 units)
        float sacc[8][4];
        #pragma unroll
        for (int n = 0; n < 8; ++n)
            sacc[n][0] = sacc[n][1] = sacc[n][2] = sacc[n][3] = 0.f;
        #pragma unroll
        for (int k = 0; k < 8; ++k) {
            uint32_t a0 = Qs[mrow * PAD + k * 8 + t];
            uint32_t a1 = Qs[(mrow + 8) * PAD + k * 8 + t];
            uint32_t a2 = Qs[mrow * PAD + k * 8 + t + 4];
            uint32_t a3 = Qs[(mrow + 8) * PAD + k * 8 + t + 4];
            #pragma unroll
            for (int n = 0; n < 8; ++n) {
                uint32_t b0 = Ks[(n * 8 + g) * PAD + k * 8 + t];
                uint32_t b1 = Ks[(n * 8 + g) * PAD + k * 8 + t + 4];
                mma_tf32(sacc[n], a0, a1, a2, a3, b0, b1);
            }
        }

        // Online softmax (intra-warp, 4-lane butterflies)
        float mx0 = sacc[0][0], mx1 = sacc[0][2];
        #pragma unroll
        for (int n = 0; n < 8; ++n) {
            mx0 = fmaxf(mx0, fmaxf(sacc[n][0], sacc[n][1]));
            mx1 = fmaxf(mx1, fmaxf(sacc[n][2], sacc[n][3]));
        }
        mx0 = fmaxf(mx0, __shfl_xor_sync(0xffffffffu, mx0, 1));
        mx0 = fmaxf(mx0, __shfl_xor_sync(0xffffffffu, mx0, 2));
        mx1 = fmaxf(mx1, __shfl_xor_sync(0xffffffffu, mx1, 1));
        mx1 = fmaxf(mx1, __shfl_xor_sync(0xffffffffu, mx1, 2));
        float mn0 = fmaxf(m0, mx0), mn1 = fmaxf(m1, mx1);
        float al0 = exp2f(m0 - mn0), al1 = exp2f(m1 - mn1);
        m0 = mn0; m1 = mn1;

        float rs0 = 0.f, rs1 = 0.f;
        #pragma unroll
        for (int n = 0; n < 8; ++n) {
            sacc[n][0] = exp2f(sacc[n][0] - mn0);
            sacc[n][1] = exp2f(sacc[n][1] - mn0);
            sacc[n][2] = exp2f(sacc[n][2] - mn1);
            sacc[n][3] = exp2f(sacc[n][3] - mn1);
            rs0 += sacc[n][0] + sacc[n][1];
            rs1 += sacc[n][2] + sacc[n][3];
        }
        rs0 += __shfl_xor_sync(0xffffffffu, rs0, 1);
        rs0 += __shfl_xor_sync(0xffffffffu, rs0, 2);
        rs1 += __shfl_xor_sync(0xffffffffu, rs1, 1);
        rs1 += __shfl_xor_sync(0xffffffffu, rs1, 2);
        l0 = l0 * al0 + rs0;
        l1 = l1 * al1 + rs1;
        #pragma unroll
        for (int n = 0; n < 8; ++n) {
            oacc[n][0] *= al0; oacc[n][1] *= al0;
            oacc[n][2] *= al1; oacc[n][3] *= al1;
        }

        __syncthreads();   // all warps done reading Ks as keys
        // P (tf32) -> Ks region: P[row][key]
        #pragma unroll
        for (int n = 0; n < 8; ++n) {
            uint2 lo2 = make_uint2(f2tf32(sacc[n][0]), f2tf32(sacc[n][1]));
            uint2 hi2 = make_uint2(f2tf32(sacc[n][2]), f2tf32(sacc[n][3]));
            *reinterpret_cast<uint2*>(&Ks[mrow * PAD + n * 8 + 2 * t])       = lo2;
            *reinterpret_cast<uint2*>(&Ks[(mrow + 8) * PAD + n * 8 + 2 * t]) = hi2;
        }
        __syncwarp();      // P rows are private to this warp

        // O += P @ V
        #pragma unroll
        for (int k = 0; k < 8; ++k) {
            uint32_t a0 = Ks[mrow * PAD + k * 8 + t];
            uint32_t a1 = Ks[(mrow + 8) * PAD + k * 8 + t];
            uint32_t a2 = Ks[mrow * PAD + k * 8 + t + 4];
            uint32_t a3 = Ks[(mrow + 8) * PAD + k * 8 + t + 4];
            #pragma unroll
            for (int n = 0; n < 8; ++n) {
                uint32_t b0 = Vs[(k * 8 + t) * PAD + n * 8 + g];
                uint32_t b1 = Vs[(k * 8 + t + 4) * PAD + n * 8 + g];
                mma_tf32(oacc[n], a0, a1, a2, a3, b0, b1);
            }
        }
    }

    // Epilogue: normalize and store.
    float inv0 = 1.0f / l0, inv1 = 1.0f / l1;
    size_t base = ((size_t)b * SS + q0) * HH;
    #pragma unroll
    for (int n = 0; n < 8; ++n) {
        float2 lo = make_float2(oacc[n][0] * inv0, oacc[n][1] * inv0);
        float2 hi = make_float2(oacc[n][2] * inv1, oacc[n][3] * inv1);
        *reinterpret_cast<float2*>(&out[base + (size_t)mrow * HH + n * 8 + 2 * t])       = lo;
        *reinterpret_cast<float2*>(&out[base + (size_t)(mrow + 8) * HH + n * 8 + 2 * t]) = hi;
    }
}

// ---------------------------------------------------------------------------
extern "C" void kernel_launch(void* const* d_in, const int* in_sizes, int n_in,
                              void* d_out, int out_size)
{
    const float* input  = (const float*)d_in[0];
    const int*   seqraw = (const int*)d_in[1];
    const float* Wq     = (const float*)d_in[2];
    const float* Wk     = (const float*)d_in[3];
    const float* Wv     = (const float*)d_in[4];
    float*       out    = (float*)d_out;

    const int tile_smem = 3 * 64 * PAD * (int)sizeof(uint32_t); // 52224
    cudaFuncSetAttribute(attn_kernel,
                         cudaFuncAttributeMaxDynamicSharedMemorySize, tile_smem);
    cudaFuncSetAttribute(proj_kernel,
                         cudaFuncAttributeMaxDynamicSharedMemorySize, tile_smem);

    normalize_seqlen_kernel<<<1, 32>>>(seqraw);
    prep_w_kernel<<<384, 256>>>(Wq, Wk, Wv);

    dim3 pgrid(MROWS / 64, 3);
    proj_kernel<<<pgrid, 128, tile_smem>>>(input);

    sumv_kernel<<<BB, 256>>>();

    attn_kernel<<<512, 128, tile_smem>>>(out);
}

// round 6
// speedup vs baseline: 3.9437x; 1.0798x over previous
#include <cuda_runtime.h>
#include <cstdint>

#define BB 16
#define SS 2048
#define EE 512
#define HH 64
#define MROWS (BB*SS)   // 32768
#define PAD 68          // smem row stride (uints): mma frag loads conflict-free

// Scratch (allocation-free rule: __device__ globals).
// q/k/v stored as tf32 bit patterns (q pre-scaled by 0.125*log2e).
__device__ uint32_t g_q[MROWS*HH];
__device__ uint32_t g_k[MROWS*HH];
__device__ uint32_t g_v[MROWS*HH];
__device__ int      g_seqlen[BB];
__device__ int      g_sched[512];          // attn work schedule: b*32 + qtile
__device__ float    g_part[BB][8][2][HH];  // sumv partials [b][chunk][tot/suf][col]
__device__ float    g_sv[BB][HH];          // suffix sum of v over t >= Lpad
__device__ float    g_tv[BB][HH];          // total sum of v over all t
__device__ uint32_t g_wt[3][HH][EE];       // W transposed, tf32: [w][n][k]

__device__ __forceinline__ uint32_t f2tf32(float x) {
    uint32_t u;
    asm("cvt.rna.tf32.f32 %0, %1;" : "=r"(u) : "f"(x));
    return u;
}

__device__ __forceinline__ void mma_tf32(float d[4], uint32_t a0, uint32_t a1,
                                         uint32_t a2, uint32_t a3,
                                         uint32_t b0, uint32_t b1) {
    asm volatile(
        "mma.sync.aligned.m16n8k8.row.col.f32.tf32.tf32.f32 "
        "{%0,%1,%2,%3}, {%4,%5,%6,%7}, {%8,%9}, {%0,%1,%2,%3};"
        : "+f"(d[0]), "+f"(d[1]), "+f"(d[2]), "+f"(d[3])
        : "r"(a0), "r"(a1), "r"(a2), "r"(a3), "r"(b0), "r"(b1));
}

__device__ __forceinline__ void cp16(uint32_t smem_addr, const void* gptr) {
    asm volatile("cp.async.cg.shared.global [%0], [%1], 16;"
                 :: "r"(smem_addr), "l"(gptr));
}
__device__ __forceinline__ void cp_commit_wait() {
    asm volatile("cp.async.commit_group;");
    asm volatile("cp.async.wait_group 0;");
}

// ---------------------------------------------------------------------------
// seq_lengths int32/int64 detection + build the attn schedule:
// real (b,qtile) units sorted by descending Lpad first, fast-path tiles last.
// ---------------------------------------------------------------------------
__global__ void normalize_seqlen_kernel(const int* __restrict__ raw)
{
    if (threadIdx.x != 0 || blockIdx.x != 0) return;
    bool looks64 = true;
    #pragma unroll
    for (int i = 0; i < 8; ++i) {
        int lo = raw[2 * i], hi = raw[2 * i + 1];
        if (hi != 0 || lo < 0 || lo > SS) looks64 = false;
    }
    int L[BB];
    #pragma unroll
    for (int b = 0; b < BB; ++b) {
        int v = looks64 ? raw[2 * b] : raw[b];
        if (v < 0) v = 0;
        if (v > SS) v = SS;
        g_seqlen[b] = v;
        L[b] = v;
    }
    int ord[BB];
    #pragma unroll
    for (int b = 0; b < BB; ++b) ord[b] = b;
    for (int i = 1; i < BB; ++i) {
        int key = ord[i];
        int kl = (L[key] + 63) & ~63;
        int j = i - 1;
        while (j >= 0 && ((L[ord[j]] + 63) & ~63) < kl) {
            ord[j + 1] = ord[j];
            --j;
        }
        ord[j + 1] = key;
    }
    int pos = 0;
    for (int i = 0; i < BB; ++i) {
        int b = ord[i];
        int nq = ((L[b] + 63) & ~63) >> 6;
        for (int qt = 0; qt < nq; ++qt) g_sched[pos++] = b * 32 + qt;
    }
    for (int i = 0; i < BB; ++i) {
        int b = ord[i];
        int nq = ((L[b] + 63) & ~63) >> 6;
        for (int qt = nq; qt < 32; ++qt) g_sched[pos++] = b * 32 + qt;
    }
}

// ---------------------------------------------------------------------------
// W transpose + tf32 convert: g_wt[w][n][k] = tf32(W[k][n]).
// ---------------------------------------------------------------------------
__global__ __launch_bounds__(256) void prep_w_kernel(
    const float* __restrict__ Wq,
    const float* __restrict__ Wk,
    const float* __restrict__ Wv)
{
    int idx = blockIdx.x * 256 + threadIdx.x;
    int w = idx >> 15;
    int rem = idx & 32767;
    int k = rem >> 6;
    int n = rem & 63;
    const float* W = (w == 0) ? Wq : (w == 1) ? Wk : Wv;
    g_wt[w][n][k] = f2tf32(W[k * HH + n]);
}

// ---------------------------------------------------------------------------
// Projection via tf32 mma with hi/lo input split. Outputs tf32 bits
// (q pre-scaled by 0.125*log2e). grid (512,3), 128 threads / 4 warps.
// ---------------------------------------------------------------------------
__global__ __launch_bounds__(128) void proj_kernel(const float* __restrict__ input)
{
    const int w    = blockIdx.y;                   // 0:q 1:k 2:v
    const int row0 = blockIdx.x * 64;
    const int batch = row0 >> 11;
    const int rin   = row0 & 2047;

    const int L    = g_seqlen[batch];
    const int Lpad = (L + 63) & ~63;
    if (w < 2 && rin >= Lpad) return;

    uint32_t* __restrict__ out = (w == 0) ? g_q : (w == 1) ? g_k : g_v;

    extern __shared__ uint32_t sm[];
    uint32_t* Ah = sm;                 // [64][PAD] tf32 hi(input)
    uint32_t* Al = Ah + 64 * PAD;      // [64][PAD] tf32 lo(input)
    uint32_t* Bs = Al + 64 * PAD;      // [64][PAD] tf32 W^T chunk: [n][kk]

    const int tid  = threadIdx.x;
    const int warp = tid >> 5;
    const int lane = tid & 31;
    const int g    = lane >> 2;
    const int t    = lane & 3;
    const int mrow = warp * 16 + g;

    float acc[8][4];
    #pragma unroll
    for (int n = 0; n < 8; ++n)
        acc[n][0] = acc[n][1] = acc[n][2] = acc[n][3] = 0.f;

    for (int c = 0; c < 8; ++c) {      // k0 = c*64
        __syncthreads();
        #pragma unroll
        for (int i = 0; i < 8; ++i) {
            int lin = tid + 128 * i;
            int r = lin >> 4, c4 = lin & 15;
            float4 av = *reinterpret_cast<const float4*>(
                &input[(size_t)(row0 + r) * EE + c * 64 + c4 * 4]);
            uint4 uh, ul;
            uh.x = f2tf32(av.x); ul.x = f2tf32(av.x - __uint_as_float(uh.x));
            uh.y = f2tf32(av.y); ul.y = f2tf32(av.y - __uint_as_float(uh.y));
            uh.z = f2tf32(av.z); ul.z = f2tf32(av.z - __uint_as_float(uh.z));
            uh.w = f2tf32(av.w); ul.w = f2tf32(av.w - __uint_as_float(uh.w));
            *reinterpret_cast<uint4*>(&Ah[r * PAD + c4 * 4]) = uh;
            *reinterpret_cast<uint4*>(&Al[r * PAD + c4 * 4]) = ul;
        }
        #pragma unroll
        for (int i = 0; i < 8; ++i) {
            int lin = tid + 128 * i;
            int n = lin >> 4, k4 = lin & 15;
            *reinterpret_cast<uint4*>(&Bs[n * PAD + k4 * 4]) =
                *reinterpret_cast<const uint4*>(&g_wt[w][n][c * 64 + k4 * 4]);
        }
        __syncthreads();

        #pragma unroll
        for (int k = 0; k < 8; ++k) {
            uint32_t ah0 = Ah[mrow * PAD + k * 8 + t];
            uint32_t ah1 = Ah[(mrow + 8) * PAD + k * 8 + t];
            uint32_t ah2 = Ah[mrow * PAD + k * 8 + t + 4];
            uint32_t ah3 = Ah[(mrow + 8) * PAD + k * 8 + t + 4];
            uint32_t al0 = Al[mrow * PAD + k * 8 + t];
            uint32_t al1 = Al[(mrow + 8) * PAD + k * 8 + t];
            uint32_t al2 = Al[mrow * PAD + k * 8 + t + 4];
            uint32_t al3 = Al[(mrow + 8) * PAD + k * 8 + t + 4];
            #pragma unroll
            for (int n = 0; n < 8; ++n) {
                uint32_t b0 = Bs[(n * 8 + g) * PAD + k * 8 + t];
                uint32_t b1 = Bs[(n * 8 + g) * PAD + k * 8 + t + 4];
                mma_tf32(acc[n], ah0, ah1, ah2, ah3, b0, b1);
                mma_tf32(acc[n], al0, al1, al2, al3, b0, b1);
            }
        }
    }

    // Epilogue: tf32-convert (+q scale), mask q/k rows >= L, store bits.
    const float sc = (w == 0) ? (0.125f * 1.4426950408889634f) : 1.0f;
    bool z0 = (w < 2) && (rin + mrow >= L);
    bool z1 = (w < 2) && (rin + mrow + 8 >= L);
    size_t base = (size_t)row0 * HH;
    #pragma unroll
    for (int n = 0; n < 8; ++n) {
        uint2 lo = z0 ? make_uint2(0u, 0u)
                      : make_uint2(f2tf32(acc[n][0] * sc), f2tf32(acc[n][1] * sc));
        uint2 hi = z1 ? make_uint2(0u, 0u)
                      : make_uint2(f2tf32(acc[n][2] * sc), f2tf32(acc[n][3] * sc));
        *reinterpret_cast<uint2*>(&out[base + (size_t)mrow * HH + n * 8 + 2 * t])       = lo;
        *reinterpret_cast<uint2*>(&out[base + (size_t)(mrow + 8) * HH + n * 8 + 2 * t]) = hi;
    }
}

// ---------------------------------------------------------------------------
// V sums, stage 1: grid (16, 8); each block reduces 256 rows -> partials.
// ---------------------------------------------------------------------------
__global__ __launch_bounds__(256) void sumv1_kernel()
{
    __shared__ float st[4][64];
    __shared__ float ss[4][64];
    const int b   = blockIdx.x;
    const int ch  = blockIdx.y;
    const int col = threadIdx.x & 63;
    const int grp = threadIdx.x >> 6;
    const int L    = g_seqlen[b];
    const int Lpad = (L + 63) & ~63;
    const uint32_t* __restrict__ vg = g_v + (size_t)b * SS * HH;

    float tot = 0.f, suf = 0.f;
    const int t0 = ch * 256;
    for (int t = t0 + grp; t < t0 + 256; t += 4) {
        float x = __uint_as_float(vg[(size_t)t * HH + col]);
        tot += x;
        if (t >= Lpad) suf += x;
    }
    st[grp][col] = tot;
    ss[grp][col] = suf;
    __syncthreads();
    if (grp == 0) {
        g_part[b][ch][0][col] = st[0][col] + st[1][col] + st[2][col] + st[3][col];
        g_part[b][ch][1][col] = ss[0][col] + ss[1][col] + ss[2][col] + ss[3][col];
    }
}

// ---------------------------------------------------------------------------
// V sums, stage 2: grid 16, 128 threads; combine 8 partials.
// ---------------------------------------------------------------------------
__global__ __launch_bounds__(128) void sumv2_kernel()
{
    const int b   = blockIdx.x;
    const int col = threadIdx.x & 63;
    const int sel = threadIdx.x >> 6;
    float s = 0.f;
    #pragma unroll
    for (int c = 0; c < 8; ++c) s += g_part[b][c][sel][col];
    if (sel == 0) g_tv[b][col] = s;
    else          g_sv[b][col] = s;
}

// ---------------------------------------------------------------------------
// Flash attention, tf32 tensor cores, schedule-driven, cp.async fills.
// q/k/v already tf32 bits in gmem (q pre-scaled).
// ---------------------------------------------------------------------------
__global__ __launch_bounds__(128) void attn_kernel(float* __restrict__ out)
{
    extern __shared__ uint32_t sm[];
    uint32_t* Qs = sm;               // [64][PAD] tf32 Q (pre-scaled)
    uint32_t* Ks = Qs + 64 * PAD;    // [64][PAD] tf32 K; P overlay
    uint32_t* Vs = Ks + 64 * PAD;    // [64][PAD] tf32 V
    const uint32_t sb = (uint32_t)__cvta_generic_to_shared(sm);
    const uint32_t Ks_off = 64 * PAD * 4;
    const uint32_t Vs_off = 128 * PAD * 4;

    const int ent = g_sched[blockIdx.x];
    const int b   = ent >> 5;
    const int q0  = (ent & 31) * 64;
    const int L    = g_seqlen[b];
    const int Lpad = (L + 63) & ~63;

    const int tid  = threadIdx.x;
    const int warp = tid >> 5;
    const int lane = tid & 31;
    const int g    = lane >> 2;
    const int t    = lane & 3;
    const int mrow = warp * 16 + g;

    // Fast path: q rows all zero -> uniform weights -> mean of all V rows.
    if (q0 >= Lpad) {
        const int c4 = tid & 15;
        const int rb = (tid >> 4) * 8;
        float4 tv = *reinterpret_cast<const float4*>(&g_tv[b][c4 * 4]);
        float4 mv;
        mv.x = tv.x * (1.0f / SS); mv.y = tv.y * (1.0f / SS);
        mv.z = tv.z * (1.0f / SS); mv.w = tv.w * (1.0f / SS);
        #pragma unroll
        for (int u = 0; u < 8; ++u)
            *reinterpret_cast<float4*>(
                &out[((size_t)b * SS + q0 + rb + u) * HH + c4 * 4]) = mv;
        return;
    }

    const uint32_t* __restrict__ qg = g_q + (size_t)b * SS * HH;
    const uint32_t* __restrict__ kg = g_k + (size_t)b * SS * HH;
    const uint32_t* __restrict__ vg = g_v + (size_t)b * SS * HH;

    // Prologue: Q tile -> smem via cp.async (bits already scaled tf32).
    #pragma unroll
    for (int i = 0; i < 8; ++i) {
        int lin = tid + 128 * i;
        int r = lin >> 4, c4 = lin & 15;
        cp16(sb + (r * PAD + c4 * 4) * 4, &qg[(size_t)(q0 + r) * HH + c4 * 4]);
    }
    cp_commit_wait();   // Q must be resident before first S-GEMM

    float m0 = 0.f, m1 = 0.f;
    float l0 = (float)(SS - Lpad), l1 = l0;
    float oacc[8][4];
    #pragma unroll
    for (int n = 0; n < 8; ++n) {
        float2 s2 = *reinterpret_cast<const float2*>(&g_sv[b][n * 8 + 2 * t]);
        oacc[n][0] = s2.x; oacc[n][1] = s2.y;
        oacc[n][2] = s2.x; oacc[n][3] = s2.y;
    }

    for (int t0 = 0; t0 < Lpad; t0 += 64) {
        __syncthreads();   // prev iter's K/V/P reads done
        #pragma unroll
        for (int i = 0; i < 8; ++i) {
            int lin = tid + 128 * i;
            int r = lin >> 4, c4 = lin & 15;
            uint32_t soff = (r * PAD + c4 * 4) * 4;
            cp16(sb + Ks_off + soff, &kg[(size_t)(t0 + r) * HH + c4 * 4]);
            cp16(sb + Vs_off + soff, &vg[(size_t)(t0 + r) * HH + c4 * 4]);
        }
        cp_commit_wait();
        __syncthreads();

        // S = Q K^T (log2 units)
        float sacc[8][4];
        #pragma unroll
        for (int n = 0; n < 8; ++n)
            sacc[n][0] = sacc[n][1] = sacc[n][2] = sacc[n][3] = 0.f;
        #pragma unroll
        for (int k = 0; k < 8; ++k) {
            uint32_t a0 = Qs[mrow * PAD + k * 8 + t];
            uint32_t a1 = Qs[(mrow + 8) * PAD + k * 8 + t];
            uint32_t a2 = Qs[mrow * PAD + k * 8 + t + 4];
            uint32_t a3 = Qs[(mrow + 8) * PAD + k * 8 + t + 4];
            #pragma unroll
            for (int n = 0; n < 8; ++n) {
                uint32_t b0 = Ks[(n * 8 + g) * PAD + k * 8 + t];
                uint32_t b1 = Ks[(n * 8 + g) * PAD + k * 8 + t + 4];
                mma_tf32(sacc[n], a0, a1, a2, a3, b0, b1);
            }
        }

        // Online softmax (intra-warp, 4-lane butterflies)
        float mx0 = sacc[0][0], mx1 = sacc[0][2];
        #pragma unroll
        for (int n = 0; n < 8; ++n) {
            mx0 = fmaxf(mx0, fmaxf(sacc[n][0], sacc[n][1]));
            mx1 = fmaxf(mx1, fmaxf(sacc[n][2], sacc[n][3]));
        }
        mx0 = fmaxf(mx0, __shfl_xor_sync(0xffffffffu, mx0, 1));
        mx0 = fmaxf(mx0, __shfl_xor_sync(0xffffffffu, mx0, 2));
        mx1 = fmaxf(mx1, __shfl_xor_sync(0xffffffffu, mx1, 1));
        mx1 = fmaxf(mx1, __shfl_xor_sync(0xffffffffu, mx1, 2));
        float mn0 = fmaxf(m0, mx0), mn1 = fmaxf(m1, mx1);
        float al0 = exp2f(m0 - mn0), al1 = exp2f(m1 - mn1);
        m0 = mn0; m1 = mn1;

        float rs0 = 0.f, rs1 = 0.f;
        #pragma unroll
        for (int n = 0; n < 8; ++n) {
            sacc[n][0] = exp2f(sacc[n][0] - mn0);
            sacc[n][1] = exp2f(sacc[n][1] - mn0);
            sacc[n][2] = exp2f(sacc[n][2] - mn1);
            sacc[n][3] = exp2f(sacc[n][3] - mn1);
            rs0 += sacc[n][0] + sacc[n][1];
            rs1 += sacc[n][2] + sacc[n][3];
        }
        rs0 += __shfl_xor_sync(0xffffffffu, rs0, 1);
        rs0 += __shfl_xor_sync(0xffffffffu, rs0, 2);
        rs1 += __shfl_xor_sync(0xffffffffu, rs1, 1);
        rs1 += __shfl_xor_sync(0xffffffffu, rs1, 2);
        l0 = l0 * al0 + rs0;
        l1 = l1 * al1 + rs1;
        #pragma unroll
        for (int n = 0; n < 8; ++n) {
            oacc[n][0] *= al0; oacc[n][1] *= al0;
            oacc[n][2] *= al1; oacc[n][3] *= al1;
        }

        __syncthreads();   // all warps done reading Ks as keys
        // P (tf32) -> Ks region: P[row][key]
        #pragma unroll
        for (int n = 0; n < 8; ++n) {
            uint2 lo2 = make_uint2(f2tf32(sacc[n][0]), f2tf32(sacc[n][1]));
            uint2 hi2 = make_uint2(f2tf32(sacc[n][2]), f2tf32(sacc[n][3]));
            *reinterpret_cast<uint2*>(&Ks[mrow * PAD + n * 8 + 2 * t])       = lo2;
            *reinterpret_cast<uint2*>(&Ks[(mrow + 8) * PAD + n * 8 + 2 * t]) = hi2;
        }
        __syncwarp();      // P rows are private to this warp

        // O += P @ V
        #pragma unroll
        for (int k = 0; k < 8; ++k) {
            uint32_t a0 = Ks[mrow * PAD + k * 8 + t];
            uint32_t a1 = Ks[(mrow + 8) * PAD + k * 8 + t];
            uint32_t a2 = Ks[mrow * PAD + k * 8 + t + 4];
            uint32_t a3 = Ks[(mrow + 8) * PAD + k * 8 + t + 4];
            #pragma unroll
            for (int n = 0; n < 8; ++n) {
                uint32_t b0 = Vs[(k * 8 + t) * PAD + n * 8 + g];
                uint32_t b1 = Vs[(k * 8 + t + 4) * PAD + n * 8 + g];
                mma_tf32(oacc[n], a0, a1, a2, a3, b0, b1);
            }
        }
    }

    // Epilogue: normalize and store.
    float inv0 = 1.0f / l0, inv1 = 1.0f / l1;
    size_t base = ((size_t)b * SS + q0) * HH;
    #pragma unroll
    for (int n = 0; n < 8; ++n) {
        float2 lo = make_float2(oacc[n][0] * inv0, oacc[n][1] * inv0);
        float2 hi = make_float2(oacc[n][2] * inv1, oacc[n][3] * inv1);
        *reinterpret_cast<float2*>(&out[base + (size_t)mrow * HH + n * 8 + 2 * t])       = lo;
        *reinterpret_cast<float2*>(&out[base + (size_t)(mrow + 8) * HH + n * 8 + 2 * t]) = hi;
    }
}

// ---------------------------------------------------------------------------
extern "C" void kernel_launch(void* const* d_in, const int* in_sizes, int n_in,
                              void* d_out, int out_size)
{
    const float* input  = (const float*)d_in[0];
    const int*   seqraw = (const int*)d_in[1];
    const float* Wq     = (const float*)d_in[2];
    const float* Wk     = (const float*)d_in[3];
    const float* Wv     = (const float*)d_in[4];
    float*       out    = (float*)d_out;

    const int tile_smem = 3 * 64 * PAD * (int)sizeof(uint32_t); // 52224
    cudaFuncSetAttribute(attn_kernel,
                         cudaFuncAttributeMaxDynamicSharedMemorySize, tile_smem);
    cudaFuncSetAttribute(proj_kernel,
                         cudaFuncAttributeMaxDynamicSharedMemorySize, tile_smem);

    normalize_seqlen_kernel<<<1, 32>>>(seqraw);
    prep_w_kernel<<<384, 256>>>(Wq, Wk, Wv);

    dim3 pgrid(MROWS / 64, 3);
    proj_kernel<<<pgrid, 128, tile_smem>>>(input);

    dim3 sgrid(BB, 8);
    sumv1_kernel<<<sgrid, 256>>>();
    sumv2_kernel<<<BB, 128>>>();

    attn_kernel<<<512, 128, tile_smem>>>(out);
}

// round 7
// speedup vs baseline: 4.2728x; 1.0835x over previous
#include <cuda_runtime.h>
#include <cstdint>

#define BB 16
#define SS 2048
#define EE 512
#define HH 64
#define MROWS (BB*SS)   // 32768
#define PAD 68          // smem row stride (uints): mma frag loads conflict-free

// Scratch (allocation-free rule: __device__ globals).
// q/k/v stored as tf32 bit patterns (q pre-scaled by 0.125*log2e).
__device__ uint32_t g_q[MROWS*HH];
__device__ uint32_t g_k[MROWS*HH];
__device__ uint32_t g_v[MROWS*HH];
__device__ int      g_seqlen[BB];
__device__ int      g_sched[256];          // attn work schedule: b*16 + qtile(128)
__device__ float    g_part[BB][8][2][HH];  // sumv partials [b][chunk][tot/suf][col]
__device__ float    g_sv[BB][HH];          // suffix sum of v over t >= Lpad
__device__ float    g_tv[BB][HH];          // total sum of v over all t
__device__ uint32_t g_wt[3][HH][EE];       // W transposed, tf32: [w][n][k]

__device__ __forceinline__ uint32_t f2tf32(float x) {
    uint32_t u;
    asm("cvt.rna.tf32.f32 %0, %1;" : "=r"(u) : "f"(x));
    return u;
}

__device__ __forceinline__ void mma_tf32(float d[4], uint32_t a0, uint32_t a1,
                                         uint32_t a2, uint32_t a3,
                                         uint32_t b0, uint32_t b1) {
    asm volatile(
        "mma.sync.aligned.m16n8k8.row.col.f32.tf32.tf32.f32 "
        "{%0,%1,%2,%3}, {%4,%5,%6,%7}, {%8,%9}, {%0,%1,%2,%3};"
        : "+f"(d[0]), "+f"(d[1]), "+f"(d[2]), "+f"(d[3])
        : "r"(a0), "r"(a1), "r"(a2), "r"(a3), "r"(b0), "r"(b1));
}

__device__ __forceinline__ void cp16(uint32_t smem_addr, const void* gptr) {
    asm volatile("cp.async.cg.shared.global [%0], [%1], 16;"
                 :: "r"(smem_addr), "l"(gptr));
}
__device__ __forceinline__ void cp_commit() {
    asm volatile("cp.async.commit_group;");
}
__device__ __forceinline__ void cp_wait0() {
    asm volatile("cp.async.wait_group 0;");
}

// ---------------------------------------------------------------------------
// seq_lengths int32/int64 detection + attn schedule (128-row q-tiles):
// real (b,qtile) units sorted by descending Lpad first, fast-path tiles last.
// ---------------------------------------------------------------------------
__global__ void normalize_seqlen_kernel(const int* __restrict__ raw)
{
    if (threadIdx.x != 0 || blockIdx.x != 0) return;
    bool looks64 = true;
    #pragma unroll
    for (int i = 0; i < 8; ++i) {
        int lo = raw[2 * i], hi = raw[2 * i + 1];
        if (hi != 0 || lo < 0 || lo > SS) looks64 = false;
    }
    int L[BB];
    #pragma unroll
    for (int b = 0; b < BB; ++b) {
        int v = looks64 ? raw[2 * b] : raw[b];
        if (v < 0) v = 0;
        if (v > SS) v = SS;
        g_seqlen[b] = v;
        L[b] = v;
    }
    int ord[BB];
    #pragma unroll
    for (int b = 0; b < BB; ++b) ord[b] = b;
    for (int i = 1; i < BB; ++i) {
        int key = ord[i];
        int kl = (L[key] + 63) & ~63;
        int j = i - 1;
        while (j >= 0 && ((L[ord[j]] + 63) & ~63) < kl) {
            ord[j + 1] = ord[j];
            --j;
        }
        ord[j + 1] = key;
    }
    int pos = 0;
    for (int i = 0; i < BB; ++i) {
        int b = ord[i];
        int Lpad = (L[b] + 63) & ~63;
        int nq = (Lpad + 127) >> 7;                // 128-row tiles with real work
        for (int qt = 0; qt < nq; ++qt) g_sched[pos++] = b * 16 + qt;
    }
    for (int i = 0; i < BB; ++i) {
        int b = ord[i];
        int Lpad = (L[b] + 63) & ~63;
        int nq = (Lpad + 127) >> 7;
        for (int qt = nq; qt < 16; ++qt) g_sched[pos++] = b * 16 + qt;
    }
}

// ---------------------------------------------------------------------------
// W transpose + tf32 convert: g_wt[w][n][k] = tf32(W[k][n]).
// ---------------------------------------------------------------------------
__global__ __launch_bounds__(256) void prep_w_kernel(
    const float* __restrict__ Wq,
    const float* __restrict__ Wk,
    const float* __restrict__ Wv)
{
    int idx = blockIdx.x * 256 + threadIdx.x;
    int w = idx >> 15;
    int rem = idx & 32767;
    int k = rem >> 6;
    int n = rem & 63;
    const float* W = (w == 0) ? Wq : (w == 1) ? Wk : Wv;
    g_wt[w][n][k] = f2tf32(W[k * HH + n]);
}

// ---------------------------------------------------------------------------
// Projection via tf32 mma with hi/lo input split. Outputs tf32 bits
// (q pre-scaled by 0.125*log2e). grid (512,3), 128 threads / 4 warps.
// ---------------------------------------------------------------------------
__global__ __launch_bounds__(128) void proj_kernel(const float* __restrict__ input)
{
    const int w    = blockIdx.y;                   // 0:q 1:k 2:v
    const int row0 = blockIdx.x * 64;
    const int batch = row0 >> 11;
    const int rin   = row0 & 2047;

    const int L    = g_seqlen[batch];
    const int Lpad = (L + 63) & ~63;
    if (w < 2 && rin >= Lpad) return;

    uint32_t* __restrict__ out = (w == 0) ? g_q : (w == 1) ? g_k : g_v;

    extern __shared__ uint32_t sm[];
    uint32_t* Ah = sm;                 // [64][PAD] tf32 hi(input)
    uint32_t* Al = Ah + 64 * PAD;      // [64][PAD] tf32 lo(input)
    uint32_t* Bs = Al + 64 * PAD;      // [64][PAD] tf32 W^T chunk: [n][kk]

    const int tid  = threadIdx.x;
    const int warp = tid >> 5;
    const int lane = tid & 31;
    const int g    = lane >> 2;
    const int t    = lane & 3;
    const int mrow = warp * 16 + g;

    float acc[8][4];
    #pragma unroll
    for (int n = 0; n < 8; ++n)
        acc[n][0] = acc[n][1] = acc[n][2] = acc[n][3] = 0.f;

    for (int c = 0; c < 8; ++c) {      // k0 = c*64
        __syncthreads();
        #pragma unroll
        for (int i = 0; i < 8; ++i) {
            int lin = tid + 128 * i;
            int r = lin >> 4, c4 = lin & 15;
            float4 av = *reinterpret_cast<const float4*>(
                &input[(size_t)(row0 + r) * EE + c * 64 + c4 * 4]);
            uint4 uh, ul;
            uh.x = f2tf32(av.x); ul.x = f2tf32(av.x - __uint_as_float(uh.x));
            uh.y = f2tf32(av.y); ul.y = f2tf32(av.y - __uint_as_float(uh.y));
            uh.z = f2tf32(av.z); ul.z = f2tf32(av.z - __uint_as_float(uh.z));
            uh.w = f2tf32(av.w); ul.w = f2tf32(av.w - __uint_as_float(uh.w));
            *reinterpret_cast<uint4*>(&Ah[r * PAD + c4 * 4]) = uh;
            *reinterpret_cast<uint4*>(&Al[r * PAD + c4 * 4]) = ul;
        }
        #pragma unroll
        for (int i = 0; i < 8; ++i) {
            int lin = tid + 128 * i;
            int n = lin >> 4, k4 = lin & 15;
            *reinterpret_cast<uint4*>(&Bs[n * PAD + k4 * 4]) =
                *reinterpret_cast<const uint4*>(&g_wt[w][n][c * 64 + k4 * 4]);
        }
        __syncthreads();

        #pragma unroll
        for (int k = 0; k < 8; ++k) {
            uint32_t ah0 = Ah[mrow * PAD + k * 8 + t];
            uint32_t ah1 = Ah[(mrow + 8) * PAD + k * 8 + t];
            uint32_t ah2 = Ah[mrow * PAD + k * 8 + t + 4];
            uint32_t ah3 = Ah[(mrow + 8) * PAD + k * 8 + t + 4];
            uint32_t al0 = Al[mrow * PAD + k * 8 + t];
            uint32_t al1 = Al[(mrow + 8) * PAD + k * 8 + t];
            uint32_t al2 = Al[mrow * PAD + k * 8 + t + 4];
            uint32_t al3 = Al[(mrow + 8) * PAD + k * 8 + t + 4];
            #pragma unroll
            for (int n = 0; n < 8; ++n) {
                uint32_t b0 = Bs[(n * 8 + g) * PAD + k * 8 + t];
                uint32_t b1 = Bs[(n * 8 + g) * PAD + k * 8 + t + 4];
                mma_tf32(acc[n], ah0, ah1, ah2, ah3, b0, b1);
                mma_tf32(acc[n], al0, al1, al2, al3, b0, b1);
            }
        }
    }

    const float sc = (w == 0) ? (0.125f * 1.4426950408889634f) : 1.0f;
    bool z0 = (w < 2) && (rin + mrow >= L);
    bool z1 = (w < 2) && (rin + mrow + 8 >= L);
    size_t base = (size_t)row0 * HH;
    #pragma unroll
    for (int n = 0; n < 8; ++n) {
        uint2 lo = z0 ? make_uint2(0u, 0u)
                      : make_uint2(f2tf32(acc[n][0] * sc), f2tf32(acc[n][1] * sc));
        uint2 hi = z1 ? make_uint2(0u, 0u)
                      : make_uint2(f2tf32(acc[n][2] * sc), f2tf32(acc[n][3] * sc));
        *reinterpret_cast<uint2*>(&out[base + (size_t)mrow * HH + n * 8 + 2 * t])       = lo;
        *reinterpret_cast<uint2*>(&out[base + (size_t)(mrow + 8) * HH + n * 8 + 2 * t]) = hi;
    }
}

// ---------------------------------------------------------------------------
// V sums, stage 1: grid (16, 8); each block reduces 256 rows -> partials.
// ---------------------------------------------------------------------------
__global__ __launch_bounds__(256) void sumv1_kernel()
{
    __shared__ float st[4][64];
    __shared__ float ss[4][64];
    const int b   = blockIdx.x;
    const int ch  = blockIdx.y;
    const int col = threadIdx.x & 63;
    const int grp = threadIdx.x >> 6;
    const int L    = g_seqlen[b];
    const int Lpad = (L + 63) & ~63;
    const uint32_t* __restrict__ vg = g_v + (size_t)b * SS * HH;

    float tot = 0.f, suf = 0.f;
    const int t0 = ch * 256;
    for (int t = t0 + grp; t < t0 + 256; t += 4) {
        float x = __uint_as_float(vg[(size_t)t * HH + col]);
        tot += x;
        if (t >= Lpad) suf += x;
    }
    st[grp][col] = tot;
    ss[grp][col] = suf;
    __syncthreads();
    if (grp == 0) {
        g_part[b][ch][0][col] = st[0][col] + st[1][col] + st[2][col] + st[3][col];
        g_part[b][ch][1][col] = ss[0][col] + ss[1][col] + ss[2][col] + ss[3][col];
    }
}

__global__ __launch_bounds__(128) void sumv2_kernel()
{
    const int b   = blockIdx.x;
    const int col = threadIdx.x & 63;
    const int sel = threadIdx.x >> 6;
    float s = 0.f;
    #pragma unroll
    for (int c = 0; c < 8; ++c) s += g_part[b][c][sel][col];
    if (sel == 0) g_tv[b][col] = s;
    else          g_sv[b][col] = s;
}

// ---------------------------------------------------------------------------
// Flash attention: 128 q-rows/block, 256 threads (8 warps, 16 rows each),
// double-buffered cp.async K/V pipeline, P->PV via in-register shuffle
// transpose (no smem P, one block sync per iteration).
// Smem: Qs[128][PAD] | K0,V0 | K1,V1  (each 64x[PAD]) = 104448 B.
// ---------------------------------------------------------------------------
__global__ __launch_bounds__(256, 2) void attn_kernel(float* __restrict__ out)
{
    extern __shared__ uint32_t sm[];
    uint32_t* Qs = sm;                          // [128][PAD]
    const uint32_t sb = (uint32_t)__cvta_generic_to_shared(sm);
    const int KV0 = 128 * PAD;                  // K buf0 | V buf0 | K buf1 | V buf1

    const int ent = g_sched[blockIdx.x];
    const int b   = ent >> 4;
    const int q0  = (ent & 15) * 128;
    const int L    = g_seqlen[b];
    const int Lpad = (L + 63) & ~63;

    const int tid  = threadIdx.x;
    const int warp = tid >> 5;
    const int lane = tid & 31;
    const int g    = lane >> 2;
    const int t    = lane & 3;
    const int mrow = warp * 16 + g;

    // Fast path: q rows all zero -> mean of all V rows.
    if (q0 >= Lpad) {
        const int c4 = tid & 15;
        const int rb = (tid >> 4) * 8;
        float4 tv = *reinterpret_cast<const float4*>(&g_tv[b][c4 * 4]);
        float4 mv;
        mv.x = tv.x * (1.0f / SS); mv.y = tv.y * (1.0f / SS);
        mv.z = tv.z * (1.0f / SS); mv.w = tv.w * (1.0f / SS);
        #pragma unroll
        for (int u = 0; u < 8; ++u)
            *reinterpret_cast<float4*>(
                &out[((size_t)b * SS + q0 + rb + u) * HH + c4 * 4]) = mv;
        return;
    }

    const uint32_t* __restrict__ qg = g_q + (size_t)b * SS * HH;
    const uint32_t* __restrict__ kg = g_k + (size_t)b * SS * HH;
    const uint32_t* __restrict__ vg = g_v + (size_t)b * SS * HH;

    // Prologue: Q (128x64) + KV tile 0 into buf0, one async group.
    #pragma unroll
    for (int i = 0; i < 8; ++i) {
        int lin = tid + 256 * i;                // 0..2047
        int r = lin >> 4, c4 = lin & 15;
        cp16(sb + (r * PAD + c4 * 4) * 4, &qg[(size_t)(q0 + r) * HH + c4 * 4]);
    }
    {
        int r = tid >> 4, c4 = tid & 15;        // 4 passes of 16 rows for K and V
        #pragma unroll
        for (int i = 0; i < 4; ++i) {
            int rr = r + 16 * i;
            uint32_t soff = (KV0 + rr * PAD + c4 * 4) * 4;
            cp16(sb + soff,                 &kg[(size_t)rr * HH + c4 * 4]);
            cp16(sb + soff + 64 * PAD * 4,  &vg[(size_t)rr * HH + c4 * 4]);
        }
    }
    cp_commit();
    cp_wait0();
    __syncthreads();

    float m0 = 0.f, m1 = 0.f;
    float l0 = (float)(SS - Lpad), l1 = l0;
    float oacc[8][4];
    #pragma unroll
    for (int n = 0; n < 8; ++n) {
        float2 s2 = *reinterpret_cast<const float2*>(&g_sv[b][n * 8 + 2 * t]);
        oacc[n][0] = s2.x; oacc[n][1] = s2.y;
        oacc[n][2] = s2.x; oacc[n][3] = s2.y;
    }

    const int nIter = Lpad >> 6;
    for (int it = 0; it < nIter; ++it) {
        const bool more = (it + 1 < nIter);
        // Prefetch next KV tile into the other buffer (overlaps with compute).
        if (more) {
            int tn = (it + 1) * 64;
            int bufn = (it + 1) & 1;
            int r = tid >> 4, c4 = tid & 15;
            #pragma unroll
            for (int i = 0; i < 4; ++i) {
                int rr = r + 16 * i;
                uint32_t soff = (KV0 + bufn * 128 * PAD + rr * PAD + c4 * 4) * 4;
                cp16(sb + soff,                &kg[(size_t)(tn + rr) * HH + c4 * 4]);
                cp16(sb + soff + 64 * PAD * 4, &vg[(size_t)(tn + rr) * HH + c4 * 4]);
            }
            cp_commit();
        }

        const uint32_t* Kc = sm + KV0 + (it & 1) * 128 * PAD;
        const uint32_t* Vc = Kc + 64 * PAD;

        // S = Q K^T (log2 units)
        float sacc[8][4];
        #pragma unroll
        for (int n = 0; n < 8; ++n)
            sacc[n][0] = sacc[n][1] = sacc[n][2] = sacc[n][3] = 0.f;
        #pragma unroll
        for (int k = 0; k < 8; ++k) {
            uint32_t a0 = Qs[mrow * PAD + k * 8 + t];
            uint32_t a1 = Qs[(mrow + 8) * PAD + k * 8 + t];
            uint32_t a2 = Qs[mrow * PAD + k * 8 + t + 4];
            uint32_t a3 = Qs[(mrow + 8) * PAD + k * 8 + t + 4];
            #pragma unroll
            for (int n = 0; n < 8; ++n) {
                uint32_t b0 = Kc[(n * 8 + g) * PAD + k * 8 + t];
                uint32_t b1 = Kc[(n * 8 + g) * PAD + k * 8 + t + 4];
                mma_tf32(sacc[n], a0, a1, a2, a3, b0, b1);
            }
        }

        // Online softmax; result rounded to tf32 bits in place.
        float mx0 = sacc[0][0], mx1 = sacc[0][2];
        #pragma unroll
        for (int n = 0; n < 8; ++n) {
            mx0 = fmaxf(mx0, fmaxf(sacc[n][0], sacc[n][1]));
            mx1 = fmaxf(mx1, fmaxf(sacc[n][2], sacc[n][3]));
        }
        mx0 = fmaxf(mx0, __shfl_xor_sync(0xffffffffu, mx0, 1));
        mx0 = fmaxf(mx0, __shfl_xor_sync(0xffffffffu, mx0, 2));
        mx1 = fmaxf(mx1, __shfl_xor_sync(0xffffffffu, mx1, 1));
        mx1 = fmaxf(mx1, __shfl_xor_sync(0xffffffffu, mx1, 2));
        float mn0 = fmaxf(m0, mx0), mn1 = fmaxf(m1, mx1);
        float al0 = exp2f(m0 - mn0), al1 = exp2f(m1 - mn1);
        m0 = mn0; m1 = mn1;

        float rs0 = 0.f, rs1 = 0.f;
        #pragma unroll
        for (int n = 0; n < 8; ++n) {
            float e0 = exp2f(sacc[n][0] - mn0);
            float e1 = exp2f(sacc[n][1] - mn0);
            float e2 = exp2f(sacc[n][2] - mn1);
            float e3 = exp2f(sacc[n][3] - mn1);
            rs0 += e0 + e1;
            rs1 += e2 + e3;
            sacc[n][0] = __uint_as_float(f2tf32(e0));
            sacc[n][1] = __uint_as_float(f2tf32(e1));
            sacc[n][2] = __uint_as_float(f2tf32(e2));
            sacc[n][3] = __uint_as_float(f2tf32(e3));
        }
        rs0 += __shfl_xor_sync(0xffffffffu, rs0, 1);
        rs0 += __shfl_xor_sync(0xffffffffu, rs0, 2);
        rs1 += __shfl_xor_sync(0xffffffffu, rs1, 1);
        rs1 += __shfl_xor_sync(0xffffffffu, rs1, 2);
        l0 = l0 * al0 + rs0;
        l1 = l1 * al1 + rs1;
        #pragma unroll
        for (int n = 0; n < 8; ++n) {
            oacc[n][0] *= al0; oacc[n][1] *= al0;
            oacc[n][2] *= al1; oacc[n][3] *= al1;
        }

        // O += P @ V with P A-frags built by in-register shuffle transpose.
        // P[row][col]: col c held by lane (g*4 + c/2), element (row half, c&1).
        const int sl0 = (lane & ~3) + (t >> 1);
        const int sl1 = sl0 + 2;
        const bool odd = (t & 1);
        #pragma unroll
        for (int k = 0; k < 8; ++k) {
            float p0 = __shfl_sync(0xffffffffu, sacc[k][0], sl0);
            float p1 = __shfl_sync(0xffffffffu, sacc[k][1], sl0);
            float p2 = __shfl_sync(0xffffffffu, sacc[k][2], sl0);
            float p3 = __shfl_sync(0xffffffffu, sacc[k][3], sl0);
            float r0 = __shfl_sync(0xffffffffu, sacc[k][0], sl1);
            float r1 = __shfl_sync(0xffffffffu, sacc[k][1], sl1);
            float r2 = __shfl_sync(0xffffffffu, sacc[k][2], sl1);
            float r3 = __shfl_sync(0xffffffffu, sacc[k][3], sl1);
            uint32_t a0 = __float_as_uint(odd ? p1 : p0);
            uint32_t a1 = __float_as_uint(odd ? p3 : p2);
            uint32_t a2 = __float_as_uint(odd ? r1 : r0);
            uint32_t a3 = __float_as_uint(odd ? r3 : r2);
            #pragma unroll
            for (int n = 0; n < 8; ++n) {
                uint32_t b0 = Vc[(k * 8 + t) * PAD + n * 8 + g];
                uint32_t b1 = Vc[(k * 8 + t + 4) * PAD + n * 8 + g];
                mma_tf32(oacc[n], a0, a1, a2, a3, b0, b1);
            }
        }

        // Drain prefetch; separates this iter's buffer reads from next writes.
        if (more) {
            cp_wait0();
            __syncthreads();
        }
    }

    // Epilogue: normalize and store.
    float inv0 = 1.0f / l0, inv1 = 1.0f / l1;
    size_t base = ((size_t)b * SS + q0) * HH;
    #pragma unroll
    for (int n = 0; n < 8; ++n) {
        float2 lo = make_float2(oacc[n][0] * inv0, oacc[n][1] * inv0);
        float2 hi = make_float2(oacc[n][2] * inv1, oacc[n][3] * inv1);
        *reinterpret_cast<float2*>(&out[base + (size_t)mrow * HH + n * 8 + 2 * t])       = lo;
        *reinterpret_cast<float2*>(&out[base + (size_t)(mrow + 8) * HH + n * 8 + 2 * t]) = hi;
    }
}

// ---------------------------------------------------------------------------
extern "C" void kernel_launch(void* const* d_in, const int* in_sizes, int n_in,
                              void* d_out, int out_size)
{
    const float* input  = (const float*)d_in[0];
    const int*   seqraw = (const int*)d_in[1];
    const float* Wq     = (const float*)d_in[2];
    const float* Wk     = (const float*)d_in[3];
    const float* Wv     = (const float*)d_in[4];
    float*       out    = (float*)d_out;

    const int proj_smem = 3 * 64 * PAD * (int)sizeof(uint32_t);          // 52224
    const int attn_smem = (128 + 4 * 64) * PAD * (int)sizeof(uint32_t);  // 104448
    cudaFuncSetAttribute(attn_kernel,
                         cudaFuncAttributeMaxDynamicSharedMemorySize, attn_smem);
    cudaFuncSetAttribute(proj_kernel,
                         cudaFuncAttributeMaxDynamicSharedMemorySize, proj_smem);

    normalize_seqlen_kernel<<<1, 32>>>(seqraw);
    prep_w_kernel<<<384, 256>>>(Wq, Wk, Wv);

    dim3 pgrid(MROWS / 64, 3);
    proj_kernel<<<pgrid, 128, proj_smem>>>(input);

    dim3 sgrid(BB, 8);
    sumv1_kernel<<<sgrid, 256>>>();
    sumv2_kernel<<<BB, 128>>>();

    attn_kernel<<<256, 256, attn_smem>>>(out);
}

// round 8
// speedup vs baseline: 4.6211x; 1.0815x over previous
#include <cuda_runtime.h>
#include <cstdint>

#define BB 16
#define SS 2048
#define EE 512
#define HH 64
#define MROWS (BB*SS)   // 32768
#define PAD 68          // smem row stride (uints): frag loads + LDSM conflict-free

// Scratch (allocation-free rule: __device__ globals).
// q/k/v stored as tf32 bit patterns (q pre-scaled by 0.125*log2e).
__device__ uint32_t g_q[MROWS*HH];
__device__ uint32_t g_k[MROWS*HH];
__device__ uint32_t g_v[MROWS*HH];
__device__ uint32_t g_vt[BB*HH*SS];        // V transposed per batch: [b][h][key]
__device__ int      g_seqlen[BB];
__device__ int      g_sched[256];          // attn work schedule: b*16 + qtile(128)
__device__ float    g_part[BB][8][2][HH];  // sumv partials [b][chunk][tot/suf][col]
__device__ float    g_sv[BB][HH];          // suffix sum of v over t >= Lpad
__device__ float    g_tv[BB][HH];          // total sum of v over all t
__device__ uint32_t g_wt[3][HH][EE];       // W transposed, tf32: [w][n][k]

__device__ __forceinline__ uint32_t f2tf32(float x) {
    uint32_t u;
    asm("cvt.rna.tf32.f32 %0, %1;" : "=r"(u) : "f"(x));
    return u;
}

__device__ __forceinline__ void mma_tf32(float d[4], uint32_t a0, uint32_t a1,
                                         uint32_t a2, uint32_t a3,
                                         uint32_t b0, uint32_t b1) {
    asm volatile(
        "mma.sync.aligned.m16n8k8.row.col.f32.tf32.tf32.f32 "
        "{%0,%1,%2,%3}, {%4,%5,%6,%7}, {%8,%9}, {%0,%1,%2,%3};"
        : "+f"(d[0]), "+f"(d[1]), "+f"(d[2]), "+f"(d[3])
        : "r"(a0), "r"(a1), "r"(a2), "r"(a3), "r"(b0), "r"(b1));
}

// ldmatrix x4 on 32-bit data: lane g*4+t of matrix i gets element [row g][col t]
// of the 8x4-f32 tile whose 8 row-addresses come from lanes 8i..8i+7.
__device__ __forceinline__ void ldsm4(uint32_t& r0, uint32_t& r1,
                                      uint32_t& r2, uint32_t& r3, uint32_t saddr) {
    asm volatile(
        "ldmatrix.sync.aligned.m8n8.x4.shared.b16 {%0,%1,%2,%3}, [%4];"
        : "=r"(r0), "=r"(r1), "=r"(r2), "=r"(r3) : "r"(saddr));
}

__device__ __forceinline__ void cp16(uint32_t smem_addr, const void* gptr) {
    asm volatile("cp.async.cg.shared.global [%0], [%1], 16;"
                 :: "r"(smem_addr), "l"(gptr));
}
__device__ __forceinline__ void cp_commit() {
    asm volatile("cp.async.commit_group;");
}
__device__ __forceinline__ void cp_wait0() {
    asm volatile("cp.async.wait_group 0;");
}

// ---------------------------------------------------------------------------
// seq_lengths int32/int64 detection + attn schedule (128-row q-tiles).
// ---------------------------------------------------------------------------
__global__ void normalize_seqlen_kernel(const int* __restrict__ raw)
{
    if (threadIdx.x != 0 || blockIdx.x != 0) return;
    bool looks64 = true;
    #pragma unroll
    for (int i = 0; i < 8; ++i) {
        int lo = raw[2 * i], hi = raw[2 * i + 1];
        if (hi != 0 || lo < 0 || lo > SS) looks64 = false;
    }
    int L[BB];
    #pragma unroll
    for (int b = 0; b < BB; ++b) {
        int v = looks64 ? raw[2 * b] : raw[b];
        if (v < 0) v = 0;
        if (v > SS) v = SS;
        g_seqlen[b] = v;
        L[b] = v;
    }
    int ord[BB];
    #pragma unroll
    for (int b = 0; b < BB; ++b) ord[b] = b;
    for (int i = 1; i < BB; ++i) {
        int key = ord[i];
        int kl = (L[key] + 63) & ~63;
        int j = i - 1;
        while (j >= 0 && ((L[ord[j]] + 63) & ~63) < kl) {
            ord[j + 1] = ord[j];
            --j;
        }
        ord[j + 1] = key;
    }
    int pos = 0;
    for (int i = 0; i < BB; ++i) {
        int b = ord[i];
        int Lpad = (L[b] + 63) & ~63;
        int nq = (Lpad + 127) >> 7;
        for (int qt = 0; qt < nq; ++qt) g_sched[pos++] = b * 16 + qt;
    }
    for (int i = 0; i < BB; ++i) {
        int b = ord[i];
        int Lpad = (L[b] + 63) & ~63;
        int nq = (Lpad + 127) >> 7;
        for (int qt = nq; qt < 16; ++qt) g_sched[pos++] = b * 16 + qt;
    }
}

// ---------------------------------------------------------------------------
// W transpose + tf32 convert: g_wt[w][n][k] = tf32(W[k][n]).
// ---------------------------------------------------------------------------
__global__ __launch_bounds__(256) void prep_w_kernel(
    const float* __restrict__ Wq,
    const float* __restrict__ Wk,
    const float* __restrict__ Wv)
{
    int idx = blockIdx.x * 256 + threadIdx.x;
    int w = idx >> 15;
    int rem = idx & 32767;
    int k = rem >> 6;
    int n = rem & 63;
    const float* W = (w == 0) ? Wq : (w == 1) ? Wk : Wv;
    g_wt[w][n][k] = f2tf32(W[k * HH + n]);
}

// ---------------------------------------------------------------------------
// Projection via tf32 mma with hi/lo input split. Outputs tf32 bits
// (q pre-scaled by 0.125*log2e; v also mirrored transposed into g_vt).
// ---------------------------------------------------------------------------
__global__ __launch_bounds__(128) void proj_kernel(const float* __restrict__ input)
{
    const int w    = blockIdx.y;                   // 0:q 1:k 2:v
    const int row0 = blockIdx.x * 64;
    const int batch = row0 >> 11;
    const int rin   = row0 & 2047;

    const int L    = g_seqlen[batch];
    const int Lpad = (L + 63) & ~63;
    if (w < 2 && rin >= Lpad) return;

    uint32_t* __restrict__ out = (w == 0) ? g_q : (w == 1) ? g_k : g_v;

    extern __shared__ uint32_t sm[];
    uint32_t* Ah = sm;                 // [64][PAD] tf32 hi(input)
    uint32_t* Al = Ah + 64 * PAD;      // [64][PAD] tf32 lo(input)
    uint32_t* Bs = Al + 64 * PAD;      // [64][PAD] tf32 W^T chunk: [n][kk]

    const int tid  = threadIdx.x;
    const int warp = tid >> 5;
    const int lane = tid & 31;
    const int g    = lane >> 2;
    const int t    = lane & 3;
    const int mrow = warp * 16 + g;

    float acc[8][4];
    #pragma unroll
    for (int n = 0; n < 8; ++n)
        acc[n][0] = acc[n][1] = acc[n][2] = acc[n][3] = 0.f;

    for (int c = 0; c < 8; ++c) {      // k0 = c*64
        __syncthreads();
        #pragma unroll
        for (int i = 0; i < 8; ++i) {
            int lin = tid + 128 * i;
            int r = lin >> 4, c4 = lin & 15;
            float4 av = *reinterpret_cast<const float4*>(
                &input[(size_t)(row0 + r) * EE + c * 64 + c4 * 4]);
            uint4 uh, ul;
            uh.x = f2tf32(av.x); ul.x = f2tf32(av.x - __uint_as_float(uh.x));
            uh.y = f2tf32(av.y); ul.y = f2tf32(av.y - __uint_as_float(uh.y));
            uh.z = f2tf32(av.z); ul.z = f2tf32(av.z - __uint_as_float(uh.z));
            uh.w = f2tf32(av.w); ul.w = f2tf32(av.w - __uint_as_float(uh.w));
            *reinterpret_cast<uint4*>(&Ah[r * PAD + c4 * 4]) = uh;
            *reinterpret_cast<uint4*>(&Al[r * PAD + c4 * 4]) = ul;
        }
        #pragma unroll
        for (int i = 0; i < 8; ++i) {
            int lin = tid + 128 * i;
            int n = lin >> 4, k4 = lin & 15;
            *reinterpret_cast<uint4*>(&Bs[n * PAD + k4 * 4]) =
                *reinterpret_cast<const uint4*>(&g_wt[w][n][c * 64 + k4 * 4]);
        }
        __syncthreads();

        #pragma unroll
        for (int k = 0; k < 8; ++k) {
            uint32_t ah0 = Ah[mrow * PAD + k * 8 + t];
            uint32_t ah1 = Ah[(mrow + 8) * PAD + k * 8 + t];
            uint32_t ah2 = Ah[mrow * PAD + k * 8 + t + 4];
            uint32_t ah3 = Ah[(mrow + 8) * PAD + k * 8 + t + 4];
            uint32_t al0 = Al[mrow * PAD + k * 8 + t];
            uint32_t al1 = Al[(mrow + 8) * PAD + k * 8 + t];
            uint32_t al2 = Al[mrow * PAD + k * 8 + t + 4];
            uint32_t al3 = Al[(mrow + 8) * PAD + k * 8 + t + 4];
            #pragma unroll
            for (int n = 0; n < 8; ++n) {
                uint32_t b0 = Bs[(n * 8 + g) * PAD + k * 8 + t];
                uint32_t b1 = Bs[(n * 8 + g) * PAD + k * 8 + t + 4];
                mma_tf32(acc[n], ah0, ah1, ah2, ah3, b0, b1);
                mma_tf32(acc[n], al0, al1, al2, al3, b0, b1);
            }
        }
    }

    const float sc = (w == 0) ? (0.125f * 1.4426950408889634f) : 1.0f;
    bool z0 = (w < 2) && (rin + mrow >= L);
    bool z1 = (w < 2) && (rin + mrow + 8 >= L);
    size_t base = (size_t)row0 * HH;
    #pragma unroll
    for (int n = 0; n < 8; ++n) {
        uint2 lo = z0 ? make_uint2(0u, 0u)
                      : make_uint2(f2tf32(acc[n][0] * sc), f2tf32(acc[n][1] * sc));
        uint2 hi = z1 ? make_uint2(0u, 0u)
                      : make_uint2(f2tf32(acc[n][2] * sc), f2tf32(acc[n][3] * sc));
        *reinterpret_cast<uint2*>(&out[base + (size_t)mrow * HH + n * 8 + 2 * t])       = lo;
        *reinterpret_cast<uint2*>(&out[base + (size_t)(mrow + 8) * HH + n * 8 + 2 * t]) = hi;
        if (w == 2) {
            // Transposed mirror for attn's PV ldmatrix path: g_vt[b][h][key]
            size_t tb = ((size_t)batch * HH + (n * 8 + 2 * t)) * SS;
            g_vt[tb + rin + mrow]          = lo.x;
            g_vt[tb + SS + rin + mrow]     = lo.y;
            g_vt[tb + rin + mrow + 8]      = hi.x;
            g_vt[tb + SS + rin + mrow + 8] = hi.y;
        }
    }
}

// ---------------------------------------------------------------------------
// V sums, stage 1 + 2 (unchanged).
// ---------------------------------------------------------------------------
__global__ __launch_bounds__(256) void sumv1_kernel()
{
    __shared__ float st[4][64];
    __shared__ float ss[4][64];
    const int b   = blockIdx.x;
    const int ch  = blockIdx.y;
    const int col = threadIdx.x & 63;
    const int grp = threadIdx.x >> 6;
    const int L    = g_seqlen[b];
    const int Lpad = (L + 63) & ~63;
    const uint32_t* __restrict__ vg = g_v + (size_t)b * SS * HH;

    float tot = 0.f, suf = 0.f;
    const int t0 = ch * 256;
    for (int t = t0 + grp; t < t0 + 256; t += 4) {
        float x = __uint_as_float(vg[(size_t)t * HH + col]);
        tot += x;
        if (t >= Lpad) suf += x;
    }
    st[grp][col] = tot;
    ss[grp][col] = suf;
    __syncthreads();
    if (grp == 0) {
        g_part[b][ch][0][col] = st[0][col] + st[1][col] + st[2][col] + st[3][col];
        g_part[b][ch][1][col] = ss[0][col] + ss[1][col] + ss[2][col] + ss[3][col];
    }
}

__global__ __launch_bounds__(128) void sumv2_kernel()
{
    const int b   = blockIdx.x;
    const int col = threadIdx.x & 63;
    const int sel = threadIdx.x >> 6;
    float s = 0.f;
    #pragma unroll
    for (int c = 0; c < 8; ++c) s += g_part[b][c][sel][col];
    if (sel == 0) g_tv[b][col] = s;
    else          g_sv[b][col] = s;
}

// ---------------------------------------------------------------------------
// Flash attention: 128 q-rows/block, 256 threads (8 warps), double-buffered
// cp.async K/V^T, ALL mma fragments fed via ldmatrix.x4 (tf32 32-bit trick),
// P via in-register shuffle transpose. One block sync per iteration.
// Smem: Qs[128][PAD] | K0,Vt0 | K1,Vt1  (each 64x[PAD]) = 104448 B.
// ---------------------------------------------------------------------------
__global__ __launch_bounds__(256, 2) void attn_kernel(float* __restrict__ out)
{
    extern __shared__ uint32_t sm[];
    const uint32_t sb = (uint32_t)__cvta_generic_to_shared(sm);
    const int KV0 = 128 * PAD;                  // K buf0 | Vt buf0 | K buf1 | Vt buf1

    const int ent = g_sched[blockIdx.x];
    const int b   = ent >> 4;
    const int q0  = (ent & 15) * 128;
    const int L    = g_seqlen[b];
    const int Lpad = (L + 63) & ~63;

    const int tid  = threadIdx.x;
    const int warp = tid >> 5;
    const int lane = tid & 31;
    const int g    = lane >> 2;
    const int t    = lane & 3;
    const int mrow = warp * 16 + g;

    // Fast path: q rows all zero -> mean of all V rows.
    if (q0 >= Lpad) {
        const int c4 = tid & 15;
        const int rb = (tid >> 4) * 8;
        float4 tv = *reinterpret_cast<const float4*>(&g_tv[b][c4 * 4]);
        float4 mv;
        mv.x = tv.x * (1.0f / SS); mv.y = tv.y * (1.0f / SS);
        mv.z = tv.z * (1.0f / SS); mv.w = tv.w * (1.0f / SS);
        #pragma unroll
        for (int u = 0; u < 8; ++u)
            *reinterpret_cast<float4*>(
                &out[((size_t)b * SS + q0 + rb + u) * HH + c4 * 4]) = mv;
        return;
    }

    const uint32_t* __restrict__ qg  = g_q  + (size_t)b * SS * HH;
    const uint32_t* __restrict__ kg  = g_k  + (size_t)b * SS * HH;
    const uint32_t* __restrict__ vtg = g_vt + (size_t)b * HH * SS;

    // Prologue: Q (128x64) + K/Vt tile 0 into buf0, one async group.
    #pragma unroll
    for (int i = 0; i < 8; ++i) {
        int lin = tid + 256 * i;                // 0..2047
        int r = lin >> 4, c4 = lin & 15;
        cp16(sb + (r * PAD + c4 * 4) * 4, &qg[(size_t)(q0 + r) * HH + c4 * 4]);
    }
    {
        int r = tid >> 4, c4 = tid & 15;
        #pragma unroll
        for (int i = 0; i < 4; ++i) {
            int rr = r + 16 * i;
            uint32_t soff = (KV0 + rr * PAD + c4 * 4) * 4;
            cp16(sb + soff,                &kg[(size_t)rr * HH + c4 * 4]);
            cp16(sb + soff + 64 * PAD * 4, &vtg[(size_t)rr * SS + c4 * 4]);
        }
    }
    cp_commit();
    cp_wait0();
    __syncthreads();

    float m0 = 0.f, m1 = 0.f;
    float l0 = (float)(SS - Lpad), l1 = l0;
    float oacc[8][4];
    #pragma unroll
    for (int n = 0; n < 8; ++n) {
        float2 s2 = *reinterpret_cast<const float2*>(&g_sv[b][n * 8 + 2 * t]);
        oacc[n][0] = s2.x; oacc[n][1] = s2.y;
        oacc[n][2] = s2.x; oacc[n][3] = s2.y;
    }

    // Lane-constant ldmatrix base addresses (byte offsets into smem).
    // Q a-frags: row 16*warp + (lane&15), col +4 f32 for lanes 16-31.
    const uint32_t qa_base = sb +
        (((16 * warp + (lane & 15)) * PAD + ((lane >> 4) << 2)) << 2);
    // K/Vt b-frags: row (lane&7) within the n*8 tile, col group (lane>>3)*4.
    const uint32_t bb_off = (((lane & 7) * PAD + ((lane >> 3) << 2)) << 2);

    const int nIter = Lpad >> 6;
    for (int it = 0; it < nIter; ++it) {
        const bool more = (it + 1 < nIter);
        if (more) {
            int tn = (it + 1) * 64;
            int bufn = (it + 1) & 1;
            int r = tid >> 4, c4 = tid & 15;
            #pragma unroll
            for (int i = 0; i < 4; ++i) {
                int rr = r + 16 * i;
                uint32_t soff = (KV0 + bufn * 128 * PAD + rr * PAD + c4 * 4) * 4;
                cp16(sb + soff,                &kg[(size_t)(tn + rr) * HH + c4 * 4]);
                cp16(sb + soff + 64 * PAD * 4, &vtg[(size_t)rr * SS + tn + c4 * 4]);
            }
            cp_commit();
        }

        const uint32_t KcA = sb + ((KV0 + (it & 1) * 128 * PAD) << 2) + bb_off;
        const uint32_t VcA = KcA + ((64 * PAD) << 2);

        // S = Q K^T (log2 units), ldmatrix-fed.
        float sacc[8][4];
        #pragma unroll
        for (int n = 0; n < 8; ++n)
            sacc[n][0] = sacc[n][1] = sacc[n][2] = sacc[n][3] = 0.f;
        #pragma unroll
        for (int j = 0; j < 4; ++j) {          // k-step pairs (2j, 2j+1)
            uint32_t a00, a01, a02, a03, a10, a11, a12, a13;
            ldsm4(a00, a01, a02, a03, qa_base + j * 64);
            ldsm4(a10, a11, a12, a13, qa_base + j * 64 + 32);
            #pragma unroll
            for (int n = 0; n < 8; ++n) {
                uint32_t b0, b1, b2, b3;
                ldsm4(b0, b1, b2, b3, KcA + ((n * 8 * PAD) << 2) + j * 64);
                mma_tf32(sacc[n], a00, a01, a02, a03, b0, b1);
                mma_tf32(sacc[n], a10, a11, a12, a13, b2, b3);
            }
        }

        // Online softmax; result rounded to tf32 bits in place.
        float mx0 = sacc[0][0], mx1 = sacc[0][2];
        #pragma unroll
        for (int n = 0; n < 8; ++n) {
            mx0 = fmaxf(mx0, fmaxf(sacc[n][0], sacc[n][1]));
            mx1 = fmaxf(mx1, fmaxf(sacc[n][2], sacc[n][3]));
        }
        mx0 = fmaxf(mx0, __shfl_xor_sync(0xffffffffu, mx0, 1));
        mx0 = fmaxf(mx0, __shfl_xor_sync(0xffffffffu, mx0, 2));
        mx1 = fmaxf(mx1, __shfl_xor_sync(0xffffffffu, mx1, 1));
        mx1 = fmaxf(mx1, __shfl_xor_sync(0xffffffffu, mx1, 2));
        float mn0 = fmaxf(m0, mx0), mn1 = fmaxf(m1, mx1);
        float al0 = exp2f(m0 - mn0), al1 = exp2f(m1 - mn1);
        m0 = mn0; m1 = mn1;

        float rs0 = 0.f, rs1 = 0.f;
        #pragma unroll
        for (int n = 0; n < 8; ++n) {
            float e0 = exp2f(sacc[n][0] - mn0);
            float e1 = exp2f(sacc[n][1] - mn0);
            float e2 = exp2f(sacc[n][2] - mn1);
            float e3 = exp2f(sacc[n][3] - mn1);
            rs0 += e0 + e1;
            rs1 += e2 + e3;
            sacc[n][0] = __uint_as_float(f2tf32(e0));
            sacc[n][1] = __uint_as_float(f2tf32(e1));
            sacc[n][2] = __uint_as_float(f2tf32(e2));
            sacc[n][3] = __uint_as_float(f2tf32(e3));
        }
        rs0 += __shfl_xor_sync(0xffffffffu, rs0, 1);
        rs0 += __shfl_xor_sync(0xffffffffu, rs0, 2);
        rs1 += __shfl_xor_sync(0xffffffffu, rs1, 1);
        rs1 += __shfl_xor_sync(0xffffffffu, rs1, 2);
        l0 = l0 * al0 + rs0;
        l1 = l1 * al1 + rs1;
        #pragma unroll
        for (int n = 0; n < 8; ++n) {
            oacc[n][0] *= al0; oacc[n][1] *= al0;
            oacc[n][2] *= al1; oacc[n][3] *= al1;
        }

        // O += P @ V: P a-frags by shuffle transpose, V^T b-frags by ldmatrix.
        const int sl0 = (lane & ~3) + (t >> 1);
        const int sl1 = sl0 + 2;
        const bool odd = (t & 1);
        #pragma unroll
        for (int j = 0; j < 4; ++j) {          // k-step pairs over keys
            uint32_t pa[2][4];
            #pragma unroll
            for (int h = 0; h < 2; ++h) {
                int k = 2 * j + h;
                float p0 = __shfl_sync(0xffffffffu, sacc[k][0], sl0);
                float p1 = __shfl_sync(0xffffffffu, sacc[k][1], sl0);
                float p2 = __shfl_sync(0xffffffffu, sacc[k][2], sl0);
                float p3 = __shfl_sync(0xffffffffu, sacc[k][3], sl0);
                float r0 = __shfl_sync(0xffffffffu, sacc[k][0], sl1);
                float r1 = __shfl_sync(0xffffffffu, sacc[k][1], sl1);
                float r2 = __shfl_sync(0xffffffffu, sacc[k][2], sl1);
                float r3 = __shfl_sync(0xffffffffu, sacc[k][3], sl1);
                pa[h][0] = __float_as_uint(odd ? p1 : p0);
                pa[h][1] = __float_as_uint(odd ? p3 : p2);
                pa[h][2] = __float_as_uint(odd ? r1 : r0);
                pa[h][3] = __float_as_uint(odd ? r3 : r2);
            }
            #pragma unroll
            for (int n = 0; n < 8; ++n) {
                uint32_t b0, b1, b2, b3;
                ldsm4(b0, b1, b2, b3, VcA + ((n * 8 * PAD) << 2) + j * 64);
                mma_tf32(oacc[n], pa[0][0], pa[0][1], pa[0][2], pa[0][3], b0, b1);
                mma_tf32(oacc[n], pa[1][0], pa[1][1], pa[1][2], pa[1][3], b2, b3);
            }
        }

        if (more) {
            cp_wait0();
            __syncthreads();
        }
    }

    // Epilogue: normalize and store.
    float inv0 = 1.0f / l0, inv1 = 1.0f / l1;
    size_t base = ((size_t)b * SS + q0) * HH;
    #pragma unroll
    for (int n = 0; n < 8; ++n) {
        float2 lo = make_float2(oacc[n][0] * inv0, oacc[n][1] * inv0);
        float2 hi = make_float2(oacc[n][2] * inv1, oacc[n][3] * inv1);
        *reinterpret_cast<float2*>(&out[base + (size_t)mrow * HH + n * 8 + 2 * t])       = lo;
        *reinterpret_cast<float2*>(&out[base + (size_t)(mrow + 8) * HH + n * 8 + 2 * t]) = hi;
    }
}

// ---------------------------------------------------------------------------
extern "C" void kernel_launch(void* const* d_in, const int* in_sizes, int n_in,
                              void* d_out, int out_size)
{
    const float* input  = (const float*)d_in[0];
    const int*   seqraw = (const int*)d_in[1];
    const float* Wq     = (const float*)d_in[2];
    const float* Wk     = (const float*)d_in[3];
    const float* Wv     = (const float*)d_in[4];
    float*       out    = (float*)d_out;

    const int proj_smem = 3 * 64 * PAD * (int)sizeof(uint32_t);          // 52224
    const int attn_smem = (128 + 4 * 64) * PAD * (int)sizeof(uint32_t);  // 104448
    cudaFuncSetAttribute(attn_kernel,
                         cudaFuncAttributeMaxDynamicSharedMemorySize, attn_smem);
    cudaFuncSetAttribute(proj_kernel,
                         cudaFuncAttributeMaxDynamicSharedMemorySize, proj_smem);

    normalize_seqlen_kernel<<<1, 32>>>(seqraw);
    prep_w_kernel<<<384, 256>>>(Wq, Wk, Wv);

    dim3 pgrid(MROWS / 64, 3);
    proj_kernel<<<pgrid, 128, proj_smem>>>(input);

    dim3 sgrid(BB, 8);
    sumv1_kernel<<<sgrid, 256>>>();
    sumv2_kernel<<<BB, 128>>>();

    attn_kernel<<<256, 256, attn_smem>>>(out);
}

// round 9
// speedup vs baseline: 4.9838x; 1.0785x over previous
#include <cuda_runtime.h>
#include <cstdint>

#define BB 16
#define SS 2048
#define EE 512
#define HH 64
#define MROWS (BB*SS)   // 32768
#define PAD 68          // smem row stride (uints): frag loads + LDSM conflict-free

// Scratch (allocation-free rule: __device__ globals).
// q/k/v stored as tf32 bit patterns (q pre-scaled by 0.125*log2e).
__device__ uint32_t g_q[MROWS*HH];
__device__ uint32_t g_k[MROWS*HH];
__device__ uint32_t g_v[MROWS*HH];
__device__ uint32_t g_vt[BB*HH*SS];        // V transposed per batch: [b][h][key]
__device__ int      g_seqlen[BB];
__device__ int      g_sched[256];          // attn work schedule: b*16 + qtile(128)
__device__ float    g_part[BB][8][2][HH];  // sumv partials [b][chunk][tot/suf][col]
__device__ float    g_sv[BB][HH];          // suffix sum of v over t >= Lpad
__device__ float    g_tv[BB][HH];          // total sum of v over all t
__device__ uint32_t g_wt[3][HH][EE];       // W transposed, tf32: [w][n][k]

__device__ __forceinline__ uint32_t f2tf32(float x) {
    uint32_t u;
    asm("cvt.rna.tf32.f32 %0, %1;" : "=r"(u) : "f"(x));
    return u;
}

__device__ __forceinline__ void mma_tf32(float d[4], uint32_t a0, uint32_t a1,
                                         uint32_t a2, uint32_t a3,
                                         uint32_t b0, uint32_t b1) {
    asm volatile(
        "mma.sync.aligned.m16n8k8.row.col.f32.tf32.tf32.f32 "
        "{%0,%1,%2,%3}, {%4,%5,%6,%7}, {%8,%9}, {%0,%1,%2,%3};"
        : "+f"(d[0]), "+f"(d[1]), "+f"(d[2]), "+f"(d[3])
        : "r"(a0), "r"(a1), "r"(a2), "r"(a3), "r"(b0), "r"(b1));
}

__device__ __forceinline__ void ldsm4(uint32_t& r0, uint32_t& r1,
                                      uint32_t& r2, uint32_t& r3, uint32_t saddr) {
    asm volatile(
        "ldmatrix.sync.aligned.m8n8.x4.shared.b16 {%0,%1,%2,%3}, [%4];"
        : "=r"(r0), "=r"(r1), "=r"(r2), "=r"(r3) : "r"(saddr));
}

__device__ __forceinline__ void cp16(uint32_t smem_addr, const void* gptr) {
    asm volatile("cp.async.cg.shared.global [%0], [%1], 16;"
                 :: "r"(smem_addr), "l"(gptr));
}
__device__ __forceinline__ void cp_commit() {
    asm volatile("cp.async.commit_group;");
}
__device__ __forceinline__ void cp_wait0() {
    asm volatile("cp.async.wait_group 0;");
}

// ---------------------------------------------------------------------------
// seq_lengths int32/int64 detection + attn schedule (128-row q-tiles).
// ---------------------------------------------------------------------------
__global__ void normalize_seqlen_kernel(const int* __restrict__ raw)
{
    if (threadIdx.x != 0 || blockIdx.x != 0) return;
    bool looks64 = true;
    #pragma unroll
    for (int i = 0; i < 8; ++i) {
        int lo = raw[2 * i], hi = raw[2 * i + 1];
        if (hi != 0 || lo < 0 || lo > SS) looks64 = false;
    }
    int L[BB];
    #pragma unroll
    for (int b = 0; b < BB; ++b) {
        int v = looks64 ? raw[2 * b] : raw[b];
        if (v < 0) v = 0;
        if (v > SS) v = SS;
        g_seqlen[b] = v;
        L[b] = v;
    }
    int ord[BB];
    #pragma unroll
    for (int b = 0; b < BB; ++b) ord[b] = b;
    for (int i = 1; i < BB; ++i) {
        int key = ord[i];
        int kl = (L[key] + 63) & ~63;
        int j = i - 1;
        while (j >= 0 && ((L[ord[j]] + 63) & ~63) < kl) {
            ord[j + 1] = ord[j];
            --j;
        }
        ord[j + 1] = key;
    }
    int pos = 0;
    for (int i = 0; i < BB; ++i) {
        int b = ord[i];
        int Lpad = (L[b] + 63) & ~63;
        int nq = (Lpad + 127) >> 7;
        for (int qt = 0; qt < nq; ++qt) g_sched[pos++] = b * 16 + qt;
    }
    for (int i = 0; i < BB; ++i) {
        int b = ord[i];
        int Lpad = (L[b] + 63) & ~63;
        int nq = (Lpad + 127) >> 7;
        for (int qt = nq; qt < 16; ++qt) g_sched[pos++] = b * 16 + qt;
    }
}

// ---------------------------------------------------------------------------
// W transpose + tf32 convert: g_wt[w][n][k] = tf32(W[k][n]).
// ---------------------------------------------------------------------------
__global__ __launch_bounds__(256) void prep_w_kernel(
    const float* __restrict__ Wq,
    const float* __restrict__ Wk,
    const float* __restrict__ Wv)
{
    int idx = blockIdx.x * 256 + threadIdx.x;
    int w = idx >> 15;
    int rem = idx & 32767;
    int k = rem >> 6;
    int n = rem & 63;
    const float* W = (w == 0) ? Wq : (w == 1) ? Wk : Wv;
    g_wt[w][n][k] = f2tf32(W[k * HH + n]);
}

// ---------------------------------------------------------------------------
// Projection, round-9: 128 rows/block, 256 threads (8 warps), double-buffered
// cp.async raw-fp32 A and tf32 B chunks, ldmatrix-fed fragments, hi/lo split
// computed in registers. Outputs tf32 bits (q pre-scaled; v mirrored to g_vt).
// Smem: Araw[2][128][PAD] | Bs[2][64][PAD] = 104448 B.
// ---------------------------------------------------------------------------
__global__ __launch_bounds__(256, 2) void proj_kernel(const float* __restrict__ input)
{
    const int w    = blockIdx.y;                   // 0:q 1:k 2:v
    const int row0 = blockIdx.x * 128;
    const int batch = row0 >> 11;
    const int rin   = row0 & 2047;

    const int L    = g_seqlen[batch];
    const int Lpad = (L + 63) & ~63;
    if (w < 2 && rin >= Lpad) return;

    uint32_t* __restrict__ out = (w == 0) ? g_q : (w == 1) ? g_k : g_v;

    extern __shared__ uint32_t sm[];
    const uint32_t sb = (uint32_t)__cvta_generic_to_shared(sm);
    const int BOFF = 256 * PAD;                    // A buf0 | A buf1 | B buf0 | B buf1

    const int tid  = threadIdx.x;
    const int warp = tid >> 5;
    const int lane = tid & 31;
    const int g    = lane >> 2;
    const int t    = lane & 3;
    const int mrow = warp * 16 + g;

    // Lane-constant ldmatrix offsets (bytes).
    const uint32_t pa_off = (((16 * warp + (lane & 15)) * PAD + ((lane >> 4) << 2)) << 2);
    const uint32_t bb_off = (((lane & 7) * PAD + ((lane >> 3) << 2)) << 2);

    // Fill chunk 0 (A raw fp32, B tf32 bits).
    {
        #pragma unroll
        for (int i = 0; i < 8; ++i) {
            int lin = tid + 256 * i;               // 0..2047
            int r = lin >> 4, c4 = lin & 15;
            cp16(sb + ((r * PAD + c4 * 4) << 2),
                 &input[(size_t)(row0 + r) * EE + c4 * 4]);
        }
        #pragma unroll
        for (int i = 0; i < 4; ++i) {
            int lin = tid + 256 * i;               // 0..1023
            int n = lin >> 4, k4 = lin & 15;
            cp16(sb + ((BOFF + n * PAD + k4 * 4) << 2), &g_wt[w][n][k4 * 4]);
        }
    }
    cp_commit();
    cp_wait0();
    __syncthreads();

    float acc[8][4];
    #pragma unroll
    for (int n = 0; n < 8; ++n)
        acc[n][0] = acc[n][1] = acc[n][2] = acc[n][3] = 0.f;

    for (int c = 0; c < 8; ++c) {      // k0 = c*64
        const bool more = (c + 1 < 8);
        if (more) {
            int bufn = (c + 1) & 1;
            #pragma unroll
            for (int i = 0; i < 8; ++i) {
                int lin = tid + 256 * i;
                int r = lin >> 4, c4 = lin & 15;
                cp16(sb + ((bufn * 128 * PAD + r * PAD + c4 * 4) << 2),
                     &input[(size_t)(row0 + r) * EE + (c + 1) * 64 + c4 * 4]);
            }
            #pragma unroll
            for (int i = 0; i < 4; ++i) {
                int lin = tid + 256 * i;
                int n = lin >> 4, k4 = lin & 15;
                cp16(sb + ((BOFF + bufn * 64 * PAD + n * PAD + k4 * 4) << 2),
                     &g_wt[w][n][(c + 1) * 64 + k4 * 4]);
            }
            cp_commit();
        }

        const uint32_t AA = sb + (((c & 1) * 128 * PAD) << 2) + pa_off;
        const uint32_t BA = sb + ((BOFF + (c & 1) * 64 * PAD) << 2) + bb_off;

        #pragma unroll
        for (int j = 0; j < 4; ++j) {              // k-step pairs (2j, 2j+1)
            uint32_t r0, r1, r2, r3, r4, r5, r6, r7;
            ldsm4(r0, r1, r2, r3, AA + j * 64);        // k-step 2j raw fp32
            ldsm4(r4, r5, r6, r7, AA + j * 64 + 32);   // k-step 2j+1 raw fp32
            uint32_t h0 = f2tf32(__uint_as_float(r0));
            uint32_t h1 = f2tf32(__uint_as_float(r1));
            uint32_t h2 = f2tf32(__uint_as_float(r2));
            uint32_t h3 = f2tf32(__uint_as_float(r3));
            uint32_t h4 = f2tf32(__uint_as_float(r4));
            uint32_t h5 = f2tf32(__uint_as_float(r5));
            uint32_t h6 = f2tf32(__uint_as_float(r6));
            uint32_t h7 = f2tf32(__uint_as_float(r7));
            uint32_t e0 = f2tf32(__uint_as_float(r0) - __uint_as_float(h0));
            uint32_t e1 = f2tf32(__uint_as_float(r1) - __uint_as_float(h1));
            uint32_t e2 = f2tf32(__uint_as_float(r2) - __uint_as_float(h2));
            uint32_t e3 = f2tf32(__uint_as_float(r3) - __uint_as_float(h3));
            uint32_t e4 = f2tf32(__uint_as_float(r4) - __uint_as_float(h4));
            uint32_t e5 = f2tf32(__uint_as_float(r5) - __uint_as_float(h5));
            uint32_t e6 = f2tf32(__uint_as_float(r6) - __uint_as_float(h6));
            uint32_t e7 = f2tf32(__uint_as_float(r7) - __uint_as_float(h7));
            #pragma unroll
            for (int n = 0; n < 8; ++n) {
                uint32_t b0, b1, b2, b3;
                ldsm4(b0, b1, b2, b3, BA + ((n * 8 * PAD) << 2) + j * 64);
                // Per-accumulator order matches round 8: hi(k), lo(k) for k=2j, 2j+1.
                mma_tf32(acc[n], h0, h1, h2, h3, b0, b1);
                mma_tf32(acc[n], e0, e1, e2, e3, b0, b1);
                mma_tf32(acc[n], h4, h5, h6, h7, b2, b3);
                mma_tf32(acc[n], e4, e5, e6, e7, b2, b3);
            }
        }

        if (more) {
            cp_wait0();
            __syncthreads();
        }
    }

    const float sc = (w == 0) ? (0.125f * 1.4426950408889634f) : 1.0f;
    bool z0 = (w < 2) && (rin + mrow >= L);
    bool z1 = (w < 2) && (rin + mrow + 8 >= L);
    size_t base = (size_t)row0 * HH;
    #pragma unroll
    for (int n = 0; n < 8; ++n) {
        uint2 lo = z0 ? make_uint2(0u, 0u)
                      : make_uint2(f2tf32(acc[n][0] * sc), f2tf32(acc[n][1] * sc));
        uint2 hi = z1 ? make_uint2(0u, 0u)
                      : make_uint2(f2tf32(acc[n][2] * sc), f2tf32(acc[n][3] * sc));
        *reinterpret_cast<uint2*>(&out[base + (size_t)mrow * HH + n * 8 + 2 * t])       = lo;
        *reinterpret_cast<uint2*>(&out[base + (size_t)(mrow + 8) * HH + n * 8 + 2 * t]) = hi;
        if (w == 2) {
            size_t tb = ((size_t)batch * HH + (n * 8 + 2 * t)) * SS;
            g_vt[tb + rin + mrow]          = lo.x;
            g_vt[tb + SS + rin + mrow]     = lo.y;
            g_vt[tb + rin + mrow + 8]      = hi.x;
            g_vt[tb + SS + rin + mrow + 8] = hi.y;
        }
    }
}

// ---------------------------------------------------------------------------
// V sums, stage 1 + 2 (unchanged).
// ---------------------------------------------------------------------------
__global__ __launch_bounds__(256) void sumv1_kernel()
{
    __shared__ float st[4][64];
    __shared__ float ss[4][64];
    const int b   = blockIdx.x;
    const int ch  = blockIdx.y;
    const int col = threadIdx.x & 63;
    const int grp = threadIdx.x >> 6;
    const int L    = g_seqlen[b];
    const int Lpad = (L + 63) & ~63;
    const uint32_t* __restrict__ vg = g_v + (size_t)b * SS * HH;

    float tot = 0.f, suf = 0.f;
    const int t0 = ch * 256;
    for (int t = t0 + grp; t < t0 + 256; t += 4) {
        float x = __uint_as_float(vg[(size_t)t * HH + col]);
        tot += x;
        if (t >= Lpad) suf += x;
    }
    st[grp][col] = tot;
    ss[grp][col] = suf;
    __syncthreads();
    if (grp == 0) {
        g_part[b][ch][0][col] = st[0][col] + st[1][col] + st[2][col] + st[3][col];
        g_part[b][ch][1][col] = ss[0][col] + ss[1][col] + ss[2][col] + ss[3][col];
    }
}

__global__ __launch_bounds__(128) void sumv2_kernel()
{
    const int b   = blockIdx.x;
    const int col = threadIdx.x & 63;
    const int sel = threadIdx.x >> 6;
    float s = 0.f;
    #pragma unroll
    for (int c = 0; c < 8; ++c) s += g_part[b][c][sel][col];
    if (sel == 0) g_tv[b][col] = s;
    else          g_sv[b][col] = s;
}

// ---------------------------------------------------------------------------
// Flash attention (unchanged from round 8): 128 q-rows/block, 256 threads,
// double-buffered cp.async K/V^T, ldmatrix-fed fragments, shuffle-P.
// ---------------------------------------------------------------------------
__global__ __launch_bounds__(256, 2) void attn_kernel(float* __restrict__ out)
{
    extern __shared__ uint32_t sm[];
    const uint32_t sb = (uint32_t)__cvta_generic_to_shared(sm);
    const int KV0 = 128 * PAD;

    const int ent = g_sched[blockIdx.x];
    const int b   = ent >> 4;
    const int q0  = (ent & 15) * 128;
    const int L    = g_seqlen[b];
    const int Lpad = (L + 63) & ~63;

    const int tid  = threadIdx.x;
    const int warp = tid >> 5;
    const int lane = tid & 31;
    const int g    = lane >> 2;
    const int t    = lane & 3;
    const int mrow = warp * 16 + g;

    if (q0 >= Lpad) {
        const int c4 = tid & 15;
        const int rb = (tid >> 4) * 8;
        float4 tv = *reinterpret_cast<const float4*>(&g_tv[b][c4 * 4]);
        float4 mv;
        mv.x = tv.x * (1.0f / SS); mv.y = tv.y * (1.0f / SS);
        mv.z = tv.z * (1.0f / SS); mv.w = tv.w * (1.0f / SS);
        #pragma unroll
        for (int u = 0; u < 8; ++u)
            *reinterpret_cast<float4*>(
                &out[((size_t)b * SS + q0 + rb + u) * HH + c4 * 4]) = mv;
        return;
    }

    const uint32_t* __restrict__ qg  = g_q  + (size_t)b * SS * HH;
    const uint32_t* __restrict__ kg  = g_k  + (size_t)b * SS * HH;
    const uint32_t* __restrict__ vtg = g_vt + (size_t)b * HH * SS;

    #pragma unroll
    for (int i = 0; i < 8; ++i) {
        int lin = tid + 256 * i;
        int r = lin >> 4, c4 = lin & 15;
        cp16(sb + (r * PAD + c4 * 4) * 4, &qg[(size_t)(q0 + r) * HH + c4 * 4]);
    }
    {
        int r = tid >> 4, c4 = tid & 15;
        #pragma unroll
        for (int i = 0; i < 4; ++i) {
            int rr = r + 16 * i;
            uint32_t soff = (KV0 + rr * PAD + c4 * 4) * 4;
            cp16(sb + soff,                &kg[(size_t)rr * HH + c4 * 4]);
            cp16(sb + soff + 64 * PAD * 4, &vtg[(size_t)rr * SS + c4 * 4]);
        }
    }
    cp_commit();
    cp_wait0();
    __syncthreads();

    float m0 = 0.f, m1 = 0.f;
    float l0 = (float)(SS - Lpad), l1 = l0;
    float oacc[8][4];
    #pragma unroll
    for (int n = 0; n < 8; ++n) {
        float2 s2 = *reinterpret_cast<const float2*>(&g_sv[b][n * 8 + 2 * t]);
        oacc[n][0] = s2.x; oacc[n][1] = s2.y;
        oacc[n][2] = s2.x; oacc[n][3] = s2.y;
    }

    const uint32_t qa_base = sb +
        (((16 * warp + (lane & 15)) * PAD + ((lane >> 4) << 2)) << 2);
    const uint32_t bb_off = (((lane & 7) * PAD + ((lane >> 3) << 2)) << 2);

    const int nIter = Lpad >> 6;
    for (int it = 0; it < nIter; ++it) {
        const bool more = (it + 1 < nIter);
        if (more) {
            int tn = (it + 1) * 64;
            int bufn = (it + 1) & 1;
            int r = tid >> 4, c4 = tid & 15;
            #pragma unroll
            for (int i = 0; i < 4; ++i) {
                int rr = r + 16 * i;
                uint32_t soff = (KV0 + bufn * 128 * PAD + rr * PAD + c4 * 4) * 4;
                cp16(sb + soff,                &kg[(size_t)(tn + rr) * HH + c4 * 4]);
                cp16(sb + soff + 64 * PAD * 4, &vtg[(size_t)rr * SS + tn + c4 * 4]);
            }
            cp_commit();
        }

        const uint32_t KcA = sb + ((KV0 + (it & 1) * 128 * PAD) << 2) + bb_off;
        const uint32_t VcA = KcA + ((64 * PAD) << 2);

        float sacc[8][4];
        #pragma unroll
        for (int n = 0; n < 8; ++n)
            sacc[n][0] = sacc[n][1] = sacc[n][2] = sacc[n][3] = 0.f;
        #pragma unroll
        for (int j = 0; j < 4; ++j) {
            uint32_t a00, a01, a02, a03, a10, a11, a12, a13;
            ldsm4(a00, a01, a02, a03, qa_base + j * 64);
            ldsm4(a10, a11, a12, a13, qa_base + j * 64 + 32);
            #pragma unroll
            for (int n = 0; n < 8; ++n) {
                uint32_t b0, b1, b2, b3;
                ldsm4(b0, b1, b2, b3, KcA + ((n * 8 * PAD) << 2) + j * 64);
                mma_tf32(sacc[n], a00, a01, a02, a03, b0, b1);
                mma_tf32(sacc[n], a10, a11, a12, a13, b2, b3);
            }
        }

        float mx0 = sacc[0][0], mx1 = sacc[0][2];
        #pragma unroll
        for (int n = 0; n < 8; ++n) {
            mx0 = fmaxf(mx0, fmaxf(sacc[n][0], sacc[n][1]));
            mx1 = fmaxf(mx1, fmaxf(sacc[n][2], sacc[n][3]));
        }
        mx0 = fmaxf(mx0, __shfl_xor_sync(0xffffffffu, mx0, 1));
        mx0 = fmaxf(mx0, __shfl_xor_sync(0xffffffffu, mx0, 2));
        mx1 = fmaxf(mx1, __shfl_xor_sync(0xffffffffu, mx1, 1));
        mx1 = fmaxf(mx1, __shfl_xor_sync(0xffffffffu, mx1, 2));
        float mn0 = fmaxf(m0, mx0), mn1 = fmaxf(m1, mx1);
        float al0 = exp2f(m0 - mn0), al1 = exp2f(m1 - mn1);
        m0 = mn0; m1 = mn1;

        float rs0 = 0.f, rs1 = 0.f;
        #pragma unroll
        for (int n = 0; n < 8; ++n) {
            float e0 = exp2f(sacc[n][0] - mn0);
            float e1 = exp2f(sacc[n][1] - mn0);
            float e2 = exp2f(sacc[n][2] - mn1);
            float e3 = exp2f(sacc[n][3] - mn1);
            rs0 += e0 + e1;
            rs1 += e2 + e3;
            sacc[n][0] = __uint_as_float(f2tf32(e0));
            sacc[n][1] = __uint_as_float(f2tf32(e1));
            sacc[n][2] = __uint_as_float(f2tf32(e2));
            sacc[n][3] = __uint_as_float(f2tf32(e3));
        }
        rs0 += __shfl_xor_sync(0xffffffffu, rs0, 1);
        rs0 += __shfl_xor_sync(0xffffffffu, rs0, 2);
        rs1 += __shfl_xor_sync(0xffffffffu, rs1, 1);
        rs1 += __shfl_xor_sync(0xffffffffu, rs1, 2);
        l0 = l0 * al0 + rs0;
        l1 = l1 * al1 + rs1;
        #pragma unroll
        for (int n = 0; n < 8; ++n) {
            oacc[n][0] *= al0; oacc[n][1] *= al0;
            oacc[n][2] *= al1; oacc[n][3] *= al1;
        }

        const int sl0 = (lane & ~3) + (t >> 1);
        const int sl1 = sl0 + 2;
        const bool odd = (t & 1);
        #pragma unroll
        for (int j = 0; j < 4; ++j) {
            uint32_t pa[2][4];
            #pragma unroll
            for (int h = 0; h < 2; ++h) {
                int k = 2 * j + h;
                float p0 = __shfl_sync(0xffffffffu, sacc[k][0], sl0);
                float p1 = __shfl_sync(0xffffffffu, sacc[k][1], sl0);
                float p2 = __shfl_sync(0xffffffffu, sacc[k][2], sl0);
                float p3 = __shfl_sync(0xffffffffu, sacc[k][3], sl0);
                float r0 = __shfl_sync(0xffffffffu, sacc[k][0], sl1);
                float r1 = __shfl_sync(0xffffffffu, sacc[k][1], sl1);
                float r2 = __shfl_sync(0xffffffffu, sacc[k][2], sl1);
                float r3 = __shfl_sync(0xffffffffu, sacc[k][3], sl1);
                pa[h][0] = __float_as_uint(odd ? p1 : p0);
                pa[h][1] = __float_as_uint(odd ? p3 : p2);
                pa[h][2] = __float_as_uint(odd ? r1 : r0);
                pa[h][3] = __float_as_uint(odd ? r3 : r2);
            }
            #pragma unroll
            for (int n = 0; n < 8; ++n) {
                uint32_t b0, b1, b2, b3;
                ldsm4(b0, b1, b2, b3, VcA + ((n * 8 * PAD) << 2) + j * 64);
                mma_tf32(oacc[n], pa[0][0], pa[0][1], pa[0][2], pa[0][3], b0, b1);
                mma_tf32(oacc[n], pa[1][0], pa[1][1], pa[1][2], pa[1][3], b2, b3);
            }
        }

        if (more) {
            cp_wait0();
            __syncthreads();
        }
    }

    float inv0 = 1.0f / l0, inv1 = 1.0f / l1;
    size_t base = ((size_t)b * SS + q0) * HH;
    #pragma unroll
    for (int n = 0; n < 8; ++n) {
        float2 lo = make_float2(oacc[n][0] * inv0, oacc[n][1] * inv0);
        float2 hi = make_float2(oacc[n][2] * inv1, oacc[n][3] * inv1);
        *reinterpret_cast<float2*>(&out[base + (size_t)mrow * HH + n * 8 + 2 * t])       = lo;
        *reinterpret_cast<float2*>(&out[base + (size_t)(mrow + 8) * HH + n * 8 + 2 * t]) = hi;
    }
}

// ---------------------------------------------------------------------------
extern "C" void kernel_launch(void* const* d_in, const int* in_sizes, int n_in,
                              void* d_out, int out_size)
{
    const float* input  = (const float*)d_in[0];
    const int*   seqraw = (const int*)d_in[1];
    const float* Wq     = (const float*)d_in[2];
    const float* Wk     = (const float*)d_in[3];
    const float* Wv     = (const float*)d_in[4];
    float*       out    = (float*)d_out;

    const int proj_smem = (2 * 128 + 2 * 64) * PAD * (int)sizeof(uint32_t); // 104448
    const int attn_smem = (128 + 4 * 64) * PAD * (int)sizeof(uint32_t);     // 104448
    cudaFuncSetAttribute(attn_kernel,
                         cudaFuncAttributeMaxDynamicSharedMemorySize, attn_smem);
    cudaFuncSetAttribute(proj_kernel,
                         cudaFuncAttributeMaxDynamicSharedMemorySize, proj_smem);

    normalize_seqlen_kernel<<<1, 32>>>(seqraw);
    prep_w_kernel<<<384, 256>>>(Wq, Wk, Wv);

    dim3 pgrid(MROWS / 128, 3);
    proj_kernel<<<pgrid, 256, proj_smem>>>(input);

    dim3 sgrid(BB, 8);
    sumv1_kernel<<<sgrid, 256>>>();
    sumv2_kernel<<<BB, 128>>>();

    attn_kernel<<<256, 256, attn_smem>>>(out);
}

// round 10
// speedup vs baseline: 5.0500x; 1.0133x over previous
#include <cuda_runtime.h>
#include <cstdint>

#define BB 16
#define SS 2048
#define EE 512
#define HH 64
#define MROWS (BB*SS)   // 32768
#define PAD 68          // smem row stride (uints): frag loads + LDSM conflict-free

// Scratch (allocation-free rule: __device__ globals).
// q/k/v stored as tf32 bit patterns (q pre-scaled by 0.125*log2e).
__device__ uint32_t g_q[MROWS*HH];
__device__ uint32_t g_k[MROWS*HH];
__device__ uint32_t g_v[MROWS*HH];
__device__ uint32_t g_vt[BB*HH*SS];         // V transposed per batch: [b][h][key]
__device__ int      g_seqlen[BB];
__device__ int      g_sched[256];           // attn work schedule: b*16 + qtile(128)
__device__ float    g_part[BB][32][2][HH];  // sumv partials [b][chunk][tot/suf][col]
__device__ float    g_sv[BB][HH];           // suffix sum of v over t >= Lpad
__device__ float    g_tv[BB][HH];           // total sum of v over all t
__device__ uint32_t g_wt[3][HH][EE];        // W transposed, tf32: [w][n][k]

__device__ __forceinline__ uint32_t f2tf32(float x) {
    uint32_t u;
    asm("cvt.rna.tf32.f32 %0, %1;" : "=r"(u) : "f"(x));
    return u;
}

// Hardware EX2 regardless of compile flags (exp2f is libm-slow w/o fast-math).
__device__ __forceinline__ float ex2(float x) {
    float y;
    asm("ex2.approx.f32 %0, %1;" : "=f"(y) : "f"(x));
    return y;
}

__device__ __forceinline__ void mma_tf32(float d[4], uint32_t a0, uint32_t a1,
                                         uint32_t a2, uint32_t a3,
                                         uint32_t b0, uint32_t b1) {
    asm volatile(
        "mma.sync.aligned.m16n8k8.row.col.f32.tf32.tf32.f32 "
        "{%0,%1,%2,%3}, {%4,%5,%6,%7}, {%8,%9}, {%0,%1,%2,%3};"
        : "+f"(d[0]), "+f"(d[1]), "+f"(d[2]), "+f"(d[3])
        : "r"(a0), "r"(a1), "r"(a2), "r"(a3), "r"(b0), "r"(b1));
}

__device__ __forceinline__ void ldsm4(uint32_t& r0, uint32_t& r1,
                                      uint32_t& r2, uint32_t& r3, uint32_t saddr) {
    asm volatile(
        "ldmatrix.sync.aligned.m8n8.x4.shared.b16 {%0,%1,%2,%3}, [%4];"
        : "=r"(r0), "=r"(r1), "=r"(r2), "=r"(r3) : "r"(saddr));
}

__device__ __forceinline__ void cp16(uint32_t smem_addr, const void* gptr) {
    asm volatile("cp.async.cg.shared.global [%0], [%1], 16;"
                 :: "r"(smem_addr), "l"(gptr));
}
__device__ __forceinline__ void cp_commit() {
    asm volatile("cp.async.commit_group;");
}
__device__ __forceinline__ void cp_wait0() {
    asm volatile("cp.async.wait_group 0;");
}

// ---------------------------------------------------------------------------
// seq_lengths int32/int64 detection + attn schedule (128-row q-tiles).
// ---------------------------------------------------------------------------
__global__ void normalize_seqlen_kernel(const int* __restrict__ raw)
{
    if (threadIdx.x != 0 || blockIdx.x != 0) return;
    bool looks64 = true;
    #pragma unroll
    for (int i = 0; i < 8; ++i) {
        int lo = raw[2 * i], hi = raw[2 * i + 1];
        if (hi != 0 || lo < 0 || lo > SS) looks64 = false;
    }
    int L[BB];
    #pragma unroll
    for (int b = 0; b < BB; ++b) {
        int v = looks64 ? raw[2 * b] : raw[b];
        if (v < 0) v = 0;
        if (v > SS) v = SS;
        g_seqlen[b] = v;
        L[b] = v;
    }
    int ord[BB];
    #pragma unroll
    for (int b = 0; b < BB; ++b) ord[b] = b;
    for (int i = 1; i < BB; ++i) {
        int key = ord[i];
        int kl = (L[key] + 63) & ~63;
        int j = i - 1;
        while (j >= 0 && ((L[ord[j]] + 63) & ~63) < kl) {
            ord[j + 1] = ord[j];
            --j;
        }
        ord[j + 1] = key;
    }
    int pos = 0;
    for (int i = 0; i < BB; ++i) {
        int b = ord[i];
        int Lpad = (L[b] + 63) & ~63;
        int nq = (Lpad + 127) >> 7;
        for (int qt = 0; qt < nq; ++qt) g_sched[pos++] = b * 16 + qt;
    }
    for (int i = 0; i < BB; ++i) {
        int b = ord[i];
        int Lpad = (L[b] + 63) & ~63;
        int nq = (Lpad + 127) >> 7;
        for (int qt = nq; qt < 16; ++qt) g_sched[pos++] = b * 16 + qt;
    }
}

// ---------------------------------------------------------------------------
// W transpose + tf32 convert: g_wt[w][n][k] = tf32(W[k][n]).
// ---------------------------------------------------------------------------
__global__ __launch_bounds__(256) void prep_w_kernel(
    const float* __restrict__ Wq,
    const float* __restrict__ Wk,
    const float* __restrict__ Wv)
{
    int idx = blockIdx.x * 256 + threadIdx.x;
    int w = idx >> 15;
    int rem = idx & 32767;
    int k = rem >> 6;
    int n = rem & 63;
    const float* W = (w == 0) ? Wq : (w == 1) ? Wk : Wv;
    g_wt[w][n][k] = f2tf32(W[k * HH + n]);
}

// ---------------------------------------------------------------------------
// Projection (unchanged from round 9): ldmatrix + hi/lo split, double-buffered.
// ---------------------------------------------------------------------------
__global__ __launch_bounds__(256, 2) void proj_kernel(const float* __restrict__ input)
{
    const int w    = blockIdx.y;                   // 0:q 1:k 2:v
    const int row0 = blockIdx.x * 128;
    const int batch = row0 >> 11;
    const int rin   = row0 & 2047;

    const int L    = g_seqlen[batch];
    const int Lpad = (L + 63) & ~63;
    if (w < 2 && rin >= Lpad) return;

    uint32_t* __restrict__ out = (w == 0) ? g_q : (w == 1) ? g_k : g_v;

    extern __shared__ uint32_t sm[];
    const uint32_t sb = (uint32_t)__cvta_generic_to_shared(sm);
    const int BOFF = 256 * PAD;

    const int tid  = threadIdx.x;
    const int warp = tid >> 5;
    const int lane = tid & 31;
    const int t    = lane & 3;
    const int g    = lane >> 2;
    const int mrow = warp * 16 + g;

    const uint32_t pa_off = (((16 * warp + (lane & 15)) * PAD + ((lane >> 4) << 2)) << 2);
    const uint32_t bb_off = (((lane & 7) * PAD + ((lane >> 3) << 2)) << 2);

    {
        #pragma unroll
        for (int i = 0; i < 8; ++i) {
            int lin = tid + 256 * i;
            int r = lin >> 4, c4 = lin & 15;
            cp16(sb + ((r * PAD + c4 * 4) << 2),
                 &input[(size_t)(row0 + r) * EE + c4 * 4]);
        }
        #pragma unroll
        for (int i = 0; i < 4; ++i) {
            int lin = tid + 256 * i;
            int n = lin >> 4, k4 = lin & 15;
            cp16(sb + ((BOFF + n * PAD + k4 * 4) << 2), &g_wt[w][n][k4 * 4]);
        }
    }
    cp_commit();
    cp_wait0();
    __syncthreads();

    float acc[8][4];
    #pragma unroll
    for (int n = 0; n < 8; ++n)
        acc[n][0] = acc[n][1] = acc[n][2] = acc[n][3] = 0.f;

    for (int c = 0; c < 8; ++c) {
        const bool more = (c + 1 < 8);
        if (more) {
            int bufn = (c + 1) & 1;
            #pragma unroll
            for (int i = 0; i < 8; ++i) {
                int lin = tid + 256 * i;
                int r = lin >> 4, c4 = lin & 15;
                cp16(sb + ((bufn * 128 * PAD + r * PAD + c4 * 4) << 2),
                     &input[(size_t)(row0 + r) * EE + (c + 1) * 64 + c4 * 4]);
            }
            #pragma unroll
            for (int i = 0; i < 4; ++i) {
                int lin = tid + 256 * i;
                int n = lin >> 4, k4 = lin & 15;
                cp16(sb + ((BOFF + bufn * 64 * PAD + n * PAD + k4 * 4) << 2),
                     &g_wt[w][n][(c + 1) * 64 + k4 * 4]);
            }
            cp_commit();
        }

        const uint32_t AA = sb + (((c & 1) * 128 * PAD) << 2) + pa_off;
        const uint32_t BA = sb + ((BOFF + (c & 1) * 64 * PAD) << 2) + bb_off;

        #pragma unroll
        for (int j = 0; j < 4; ++j) {
            uint32_t r0, r1, r2, r3, r4, r5, r6, r7;
            ldsm4(r0, r1, r2, r3, AA + j * 64);
            ldsm4(r4, r5, r6, r7, AA + j * 64 + 32);
            uint32_t h0 = f2tf32(__uint_as_float(r0));
            uint32_t h1 = f2tf32(__uint_as_float(r1));
            uint32_t h2 = f2tf32(__uint_as_float(r2));
            uint32_t h3 = f2tf32(__uint_as_float(r3));
            uint32_t h4 = f2tf32(__uint_as_float(r4));
            uint32_t h5 = f2tf32(__uint_as_float(r5));
            uint32_t h6 = f2tf32(__uint_as_float(r6));
            uint32_t h7 = f2tf32(__uint_as_float(r7));
            uint32_t e0 = f2tf32(__uint_as_float(r0) - __uint_as_float(h0));
            uint32_t e1 = f2tf32(__uint_as_float(r1) - __uint_as_float(h1));
            uint32_t e2 = f2tf32(__uint_as_float(r2) - __uint_as_float(h2));
            uint32_t e3 = f2tf32(__uint_as_float(r3) - __uint_as_float(h3));
            uint32_t e4 = f2tf32(__uint_as_float(r4) - __uint_as_float(h4));
            uint32_t e5 = f2tf32(__uint_as_float(r5) - __uint_as_float(h5));
            uint32_t e6 = f2tf32(__uint_as_float(r6) - __uint_as_float(h6));
            uint32_t e7 = f2tf32(__uint_as_float(r7) - __uint_as_float(h7));
            #pragma unroll
            for (int n = 0; n < 8; ++n) {
                uint32_t b0, b1, b2, b3;
                ldsm4(b0, b1, b2, b3, BA + ((n * 8 * PAD) << 2) + j * 64);
                mma_tf32(acc[n], h0, h1, h2, h3, b0, b1);
                mma_tf32(acc[n], e0, e1, e2, e3, b0, b1);
                mma_tf32(acc[n], h4, h5, h6, h7, b2, b3);
                mma_tf32(acc[n], e4, e5, e6, e7, b2, b3);
            }
        }

        if (more) {
            cp_wait0();
            __syncthreads();
        }
    }

    const float sc = (w == 0) ? (0.125f * 1.4426950408889634f) : 1.0f;
    bool z0 = (w < 2) && (rin + mrow >= L);
    bool z1 = (w < 2) && (rin + mrow + 8 >= L);
    size_t base = (size_t)row0 * HH;
    #pragma unroll
    for (int n = 0; n < 8; ++n) {
        uint2 lo = z0 ? make_uint2(0u, 0u)
                      : make_uint2(f2tf32(acc[n][0] * sc), f2tf32(acc[n][1] * sc));
        uint2 hi = z1 ? make_uint2(0u, 0u)
                      : make_uint2(f2tf32(acc[n][2] * sc), f2tf32(acc[n][3] * sc));
        *reinterpret_cast<uint2*>(&out[base + (size_t)mrow * HH + n * 8 + 2 * t])       = lo;
        *reinterpret_cast<uint2*>(&out[base + (size_t)(mrow + 8) * HH + n * 8 + 2 * t]) = hi;
        if (w == 2) {
            size_t tb = ((size_t)batch * HH + (n * 8 + 2 * t)) * SS;
            g_vt[tb + rin + mrow]          = lo.x;
            g_vt[tb + SS + rin + mrow]     = lo.y;
            g_vt[tb + rin + mrow + 8]      = hi.x;
            g_vt[tb + SS + rin + mrow + 8] = hi.y;
        }
    }
}

// ---------------------------------------------------------------------------
// V sums, stage 1: grid (16, 32); each block reduces 64 rows -> partials.
// More blocks = more loads in flight on this latency-bound stream.
// ---------------------------------------------------------------------------
__global__ __launch_bounds__(256) void sumv1_kernel()
{
    __shared__ float st[4][64];
    __shared__ float ss[4][64];
    const int b   = blockIdx.x;
    const int ch  = blockIdx.y;
    const int col = threadIdx.x & 63;
    const int grp = threadIdx.x >> 6;
    const int L    = g_seqlen[b];
    const int Lpad = (L + 63) & ~63;
    const uint32_t* __restrict__ vg = g_v + (size_t)b * SS * HH;

    float tot = 0.f, suf = 0.f;
    const int t0 = ch * 64;
    #pragma unroll
    for (int i = 0; i < 16; ++i) {
        int t = t0 + grp + 4 * i;
        float x = __uint_as_float(vg[(size_t)t * HH + col]);
        tot += x;
        if (t >= Lpad) suf += x;
    }
    st[grp][col] = tot;
    ss[grp][col] = suf;
    __syncthreads();
    if (grp == 0) {
        g_part[b][ch][0][col] = st[0][col] + st[1][col] + st[2][col] + st[3][col];
        g_part[b][ch][1][col] = ss[0][col] + ss[1][col] + ss[2][col] + ss[3][col];
    }
}

__global__ __launch_bounds__(128) void sumv2_kernel()
{
    const int b   = blockIdx.x;
    const int col = threadIdx.x & 63;
    const int sel = threadIdx.x >> 6;
    float s = 0.f;
    #pragma unroll
    for (int c = 0; c < 32; ++c) s += g_part[b][c][sel][col];
    if (sel == 0) g_tv[b][col] = s;
    else          g_sv[b][col] = s;
}

// ---------------------------------------------------------------------------
// Flash attention: round-8 structure, exponentials forced to MUFU EX2.
// ---------------------------------------------------------------------------
__global__ __launch_bounds__(256, 2) void attn_kernel(float* __restrict__ out)
{
    extern __shared__ uint32_t sm[];
    const uint32_t sb = (uint32_t)__cvta_generic_to_shared(sm);
    const int KV0 = 128 * PAD;

    const int ent = g_sched[blockIdx.x];
    const int b   = ent >> 4;
    const int q0  = (ent & 15) * 128;
    const int L    = g_seqlen[b];
    const int Lpad = (L + 63) & ~63;

    const int tid  = threadIdx.x;
    const int warp = tid >> 5;
    const int lane = tid & 31;
    const int g    = lane >> 2;
    const int t    = lane & 3;
    const int mrow = warp * 16 + g;

    if (q0 >= Lpad) {
        const int c4 = tid & 15;
        const int rb = (tid >> 4) * 8;
        float4 tv = *reinterpret_cast<const float4*>(&g_tv[b][c4 * 4]);
        float4 mv;
        mv.x = tv.x * (1.0f / SS); mv.y = tv.y * (1.0f / SS);
        mv.z = tv.z * (1.0f / SS); mv.w = tv.w * (1.0f / SS);
        #pragma unroll
        for (int u = 0; u < 8; ++u)
            *reinterpret_cast<float4*>(
                &out[((size_t)b * SS + q0 + rb + u) * HH + c4 * 4]) = mv;
        return;
    }

    const uint32_t* __restrict__ qg  = g_q  + (size_t)b * SS * HH;
    const uint32_t* __restrict__ kg  = g_k  + (size_t)b * SS * HH;
    const uint32_t* __restrict__ vtg = g_vt + (size_t)b * HH * SS;

    #pragma unroll
    for (int i = 0; i < 8; ++i) {
        int lin = tid + 256 * i;
        int r = lin >> 4, c4 = lin & 15;
        cp16(sb + (r * PAD + c4 * 4) * 4, &qg[(size_t)(q0 + r) * HH + c4 * 4]);
    }
    {
        int r = tid >> 4, c4 = tid & 15;
        #pragma unroll
        for (int i = 0; i < 4; ++i) {
            int rr = r + 16 * i;
            uint32_t soff = (KV0 + rr * PAD + c4 * 4) * 4;
            cp16(sb + soff,                &kg[(size_t)rr * HH + c4 * 4]);
            cp16(sb + soff + 64 * PAD * 4, &vtg[(size_t)rr * SS + c4 * 4]);
        }
    }
    cp_commit();
    cp_wait0();
    __syncthreads();

    float m0 = 0.f, m1 = 0.f;
    float l0 = (float)(SS - Lpad), l1 = l0;
    float oacc[8][4];
    #pragma unroll
    for (int n = 0; n < 8; ++n) {
        float2 s2 = *reinterpret_cast<const float2*>(&g_sv[b][n * 8 + 2 * t]);
        oacc[n][0] = s2.x; oacc[n][1] = s2.y;
        oacc[n][2] = s2.x; oacc[n][3] = s2.y;
    }

    const uint32_t qa_base = sb +
        (((16 * warp + (lane & 15)) * PAD + ((lane >> 4) << 2)) << 2);
    const uint32_t bb_off = (((lane & 7) * PAD + ((lane >> 3) << 2)) << 2);

    const int nIter = Lpad >> 6;
    for (int it = 0; it < nIter; ++it) {
        const bool more = (it + 1 < nIter);
        if (more) {
            int tn = (it + 1) * 64;
            int bufn = (it + 1) & 1;
            int r = tid >> 4, c4 = tid & 15;
            #pragma unroll
            for (int i = 0; i < 4; ++i) {
                int rr = r + 16 * i;
                uint32_t soff = (KV0 + bufn * 128 * PAD + rr * PAD + c4 * 4) * 4;
                cp16(sb + soff,                &kg[(size_t)(tn + rr) * HH + c4 * 4]);
                cp16(sb + soff + 64 * PAD * 4, &vtg[(size_t)rr * SS + tn + c4 * 4]);
            }
            cp_commit();
        }

        const uint32_t KcA = sb + ((KV0 + (it & 1) * 128 * PAD) << 2) + bb_off;
        const uint32_t VcA = KcA + ((64 * PAD) << 2);

        float sacc[8][4];
        #pragma unroll
        for (int n = 0; n < 8; ++n)
            sacc[n][0] = sacc[n][1] = sacc[n][2] = sacc[n][3] = 0.f;
        #pragma unroll
        for (int j = 0; j < 4; ++j) {
            uint32_t a00, a01, a02, a03, a10, a11, a12, a13;
            ldsm4(a00, a01, a02, a03, qa_base + j * 64);
            ldsm4(a10, a11, a12, a13, qa_base + j * 64 + 32);
            #pragma unroll
            for (int n = 0; n < 8; ++n) {
                uint32_t b0, b1, b2, b3;
                ldsm4(b0, b1, b2, b3, KcA + ((n * 8 * PAD) << 2) + j * 64);
                mma_tf32(sacc[n], a00, a01, a02, a03, b0, b1);
                mma_tf32(sacc[n], a10, a11, a12, a13, b2, b3);
            }
        }

        float mx0 = sacc[0][0], mx1 = sacc[0][2];
        #pragma unroll
        for (int n = 0; n < 8; ++n) {
            mx0 = fmaxf(mx0, fmaxf(sacc[n][0], sacc[n][1]));
            mx1 = fmaxf(mx1, fmaxf(sacc[n][2], sacc[n][3]));
        }
        mx0 = fmaxf(mx0, __shfl_xor_sync(0xffffffffu, mx0, 1));
        mx0 = fmaxf(mx0, __shfl_xor_sync(0xffffffffu, mx0, 2));
        mx1 = fmaxf(mx1, __shfl_xor_sync(0xffffffffu, mx1, 1));
        mx1 = fmaxf(mx1, __shfl_xor_sync(0xffffffffu, mx1, 2));
        float mn0 = fmaxf(m0, mx0), mn1 = fmaxf(m1, mx1);
        float al0 = ex2(m0 - mn0), al1 = ex2(m1 - mn1);
        m0 = mn0; m1 = mn1;

        float rs0 = 0.f, rs1 = 0.f;
        #pragma unroll
        for (int n = 0; n < 8; ++n) {
            float e0 = ex2(sacc[n][0] - mn0);
            float e1 = ex2(sacc[n][1] - mn0);
            float e2 = ex2(sacc[n][2] - mn1);
            float e3 = ex2(sacc[n][3] - mn1);
            rs0 += e0 + e1;
            rs1 += e2 + e3;
            sacc[n][0] = __uint_as_float(f2tf32(e0));
            sacc[n][1] = __uint_as_float(f2tf32(e1));
            sacc[n][2] = __uint_as_float(f2tf32(e2));
            sacc[n][3] = __uint_as_float(f2tf32(e3));
        }
        rs0 += __shfl_xor_sync(0xffffffffu, rs0, 1);
        rs0 += __shfl_xor_sync(0xffffffffu, rs0, 2);
        rs1 += __shfl_xor_sync(0xffffffffu, rs1, 1);
        rs1 += __shfl_xor_sync(0xffffffffu, rs1, 2);
        l0 = l0 * al0 + rs0;
        l1 = l1 * al1 + rs1;
        #pragma unroll
        for (int n = 0; n < 8; ++n) {
            oacc[n][0] *= al0; oacc[n][1] *= al0;
            oacc[n][2] *= al1; oacc[n][3] *= al1;
        }

        const int sl0 = (lane & ~3) + (t >> 1);
        const int sl1 = sl0 + 2;
        const bool odd = (t & 1);
        #pragma unroll
        for (int j = 0; j < 4; ++j) {
            uint32_t pa[2][4];
            #pragma unroll
            for (int h = 0; h < 2; ++h) {
                int k = 2 * j + h;
                float p0 = __shfl_sync(0xffffffffu, sacc[k][0], sl0);
                float p1 = __shfl_sync(0xffffffffu, sacc[k][1], sl0);
                float p2 = __shfl_sync(0xffffffffu, sacc[k][2], sl0);
                float p3 = __shfl_sync(0xffffffffu, sacc[k][3], sl0);
                float r0 = __shfl_sync(0xffffffffu, sacc[k][0], sl1);
                float r1 = __shfl_sync(0xffffffffu, sacc[k][1], sl1);
                float r2 = __shfl_sync(0xffffffffu, sacc[k][2], sl1);
                float r3 = __shfl_sync(0xffffffffu, sacc[k][3], sl1);
                pa[h][0] = __float_as_uint(odd ? p1 : p0);
                pa[h][1] = __float_as_uint(odd ? p3 : p2);
                pa[h][2] = __float_as_uint(odd ? r1 : r0);
                pa[h][3] = __float_as_uint(odd ? r3 : r2);
            }
            #pragma unroll
            for (int n = 0; n < 8; ++n) {
                uint32_t b0, b1, b2, b3;
                ldsm4(b0, b1, b2, b3, VcA + ((n * 8 * PAD) << 2) + j * 64);
                mma_tf32(oacc[n], pa[0][0], pa[0][1], pa[0][2], pa[0][3], b0, b1);
                mma_tf32(oacc[n], pa[1][0], pa[1][1], pa[1][2], pa[1][3], b2, b3);
            }
        }

        if (more) {
            cp_wait0();
            __syncthreads();
        }
    }

    float inv0 = 1.0f / l0, inv1 = 1.0f / l1;
    size_t base = ((size_t)b * SS + q0) * HH;
    #pragma unroll
    for (int n = 0; n < 8; ++n) {
        float2 lo = make_float2(oacc[n][0] * inv0, oacc[n][1] * inv0);
        float2 hi = make_float2(oacc[n][2] * inv1, oacc[n][3] * inv1);
        *reinterpret_cast<float2*>(&out[base + (size_t)mrow * HH + n * 8 + 2 * t])       = lo;
        *reinterpret_cast<float2*>(&out[base + (size_t)(mrow + 8) * HH + n * 8 + 2 * t]) = hi;
    }
}

// ---------------------------------------------------------------------------
extern "C" void kernel_launch(void* const* d_in, const int* in_sizes, int n_in,
                              void* d_out, int out_size)
{
    const float* input  = (const float*)d_in[0];
    const int*   seqraw = (const int*)d_in[1];
    const float* Wq     = (const float*)d_in[2];
    const float* Wk     = (const float*)d_in[3];
    const float* Wv     = (const float*)d_in[4];
    float*       out    = (float*)d_out;

    const int proj_smem = (2 * 128 + 2 * 64) * PAD * (int)sizeof(uint32_t); // 104448
    const int attn_smem = (128 + 4 * 64) * PAD * (int)sizeof(uint32_t);     // 104448
    cudaFuncSetAttribute(attn_kernel,
                         cudaFuncAttributeMaxDynamicSharedMemorySize, attn_smem);
    cudaFuncSetAttribute(proj_kernel,
                         cudaFuncAttributeMaxDynamicSharedMemorySize, proj_smem);

    normalize_seqlen_kernel<<<1, 32>>>(seqraw);
    prep_w_kernel<<<384, 256>>>(Wq, Wk, Wv);

    dim3 pgrid(MROWS / 128, 3);
    proj_kernel<<<pgrid, 256, proj_smem>>>(input);

    dim3 sgrid(BB, 32);
    sumv1_kernel<<<sgrid, 256>>>();
    sumv2_kernel<<<BB, 128>>>();

    attn_kernel<<<256, 256, attn_smem>>>(out);
}